// round 7
// baseline (speedup 1.0000x reference)
#include <cuda_runtime.h>
#include <cuda_bf16.h>
#include <math.h>
#include <stdint.h>

// Problem constants
#define E_  8
#define D_  1024
#define F_  4096
#define T_  8192
#define TK_ (T_ * 2)

// GEMM tiling: 128x128 block, KC=32 chunk (64B bf16 rows, SW64 swizzle),
// 512 threads (16 warps, 4/SMSP), warp tile 32x32, 3-stage cp.async pipeline.
#define BM 128
#define BN 128
#define KC 32
#define NTH 512
#define AH_OFF 0
#define AL_OFF 8192
#define BH_OFF 16384
#define BL_OFF 24576
#define STAGE_B 32768
#define NSTAGE 3
#define SMEM_DYN (NSTAGE * STAGE_B)   // 96 KB

// ---------------------------------------------------------------------------
// Device scratch (static: no allocations allowed)
// ---------------------------------------------------------------------------
__device__ __nv_bfloat16 g_xh[(size_t)T_ * D_];
__device__ __nv_bfloat16 g_xl[(size_t)T_ * D_];
__device__ __nv_bfloat16 g_wfh[(size_t)E_ * F_ * D_];
__device__ __nv_bfloat16 g_wfl[(size_t)E_ * F_ * D_];
__device__ __nv_bfloat16 g_wph[(size_t)E_ * D_ * F_];
__device__ __nv_bfloat16 g_wpl[(size_t)E_ * D_ * F_];
__device__ __nv_bfloat16 g_hh[(size_t)TK_ * F_];
__device__ __nv_bfloat16 g_hl[(size_t)TK_ * F_];
__device__ int   g_tok[E_ * T_];
__device__ float g_wgt[E_ * T_];
__device__ int   g_cursor[E_];
__device__ int   g_base[E_];

// ---------------------------------------------------------------------------
// Helpers
// ---------------------------------------------------------------------------
static __device__ __forceinline__ uint32_t smem_u32(const void* p) {
    uint32_t a;
    asm("{ .reg .u64 t; cvta.to.shared.u64 t, %1; cvt.u32.u64 %0, t; }"
        : "=r"(a) : "l"(p));
    return a;
}

// 64B-row swizzle: XOR 16B-unit bits [4:5] with row bits 1-2 (o bits [7:8]).
// 8-row ldmatrix octet: even rows hit 4 distinct 16B columns in [0,64),
// odd rows 4 distinct in [64,128) -> 32 distinct banks, conflict-free.
#define SW64(o) ((o) ^ (((o) >> 3) & 0x30))

#define CPA(dst, src) \
    asm volatile("cp.async.cg.shared.global [%0], [%1], 16;" \
                 :: "r"(dst), "l"(src) : "memory")
#define CPA_COMMIT() asm volatile("cp.async.commit_group;" ::: "memory")

#define LDSM4(r, addr) \
    asm volatile("ldmatrix.sync.aligned.m8n8.x4.shared.b16 {%0,%1,%2,%3}, [%4];" \
                 : "=r"((r)[0]), "=r"((r)[1]), "=r"((r)[2]), "=r"((r)[3]) \
                 : "r"(addr))

#define MMA(cd, a, b0, b1) \
    asm volatile("mma.sync.aligned.m16n8k16.row.col.f32.bf16.bf16.f32 " \
                 "{%0,%1,%2,%3}, {%4,%5,%6,%7}, {%8,%9}, {%0,%1,%2,%3};" \
                 : "+f"((cd)[0]), "+f"((cd)[1]), "+f"((cd)[2]), "+f"((cd)[3]) \
                 : "r"((a)[0]), "r"((a)[1]), "r"((a)[2]), "r"((a)[3]), \
                   "r"(b0), "r"(b1))

static __device__ __forceinline__ float ngelu(float v) {
    float u = 0.7978845608028654f * (v + 0.044715f * v * v * v);
    return 0.5f * v * (1.0f + tanhf(u));
}

// One K=32 chunk of the 3-term split MMA (Ah*Bh + Ah*Bl + Al*Bh).
// Warp tile 32(M) x 32(N): 2 M-frags, 4 N-frags, 32 accumulators.
static __device__ __forceinline__ void mma_chunk(
    uint32_t bufb, int warp_m, int warp_n,
    int rA, int bA, int rB, int bB, float (&c)[2][4][4]) {
#pragma unroll
    for (int ks = 0; ks < 2; ks++) {
        int kb = ks * 32;
        uint32_t Af[2][4], Bh[2][4], Bl[2][4];
#pragma unroll
        for (int f = 0; f < 2; f++) {
            uint32_t off = (uint32_t)((warp_m * 32 + f * 16 + rA) * 64 + kb + bA);
            LDSM4(Af[f], bufb + AH_OFF + SW64(off));
        }
#pragma unroll
        for (int p = 0; p < 2; p++) {
            uint32_t off = (uint32_t)((warp_n * 32 + p * 16 + rB) * 64 + kb + bB);
            LDSM4(Bh[p], bufb + BH_OFF + SW64(off));
        }
#pragma unroll
        for (int p = 0; p < 2; p++) {
            uint32_t off = (uint32_t)((warp_n * 32 + p * 16 + rB) * 64 + kb + bB);
            LDSM4(Bl[p], bufb + BL_OFF + SW64(off));
        }
#pragma unroll
        for (int f = 0; f < 2; f++)
#pragma unroll
            for (int nf = 0; nf < 4; nf++)
                MMA(c[f][nf], Af[f], Bh[nf >> 1][(nf & 1) * 2], Bh[nf >> 1][(nf & 1) * 2 + 1]);
#pragma unroll
        for (int f = 0; f < 2; f++)
#pragma unroll
            for (int nf = 0; nf < 4; nf++)
                MMA(c[f][nf], Af[f], Bl[nf >> 1][(nf & 1) * 2], Bl[nf >> 1][(nf & 1) * 2 + 1]);
        // reload A with lo part (reuses Af registers)
#pragma unroll
        for (int f = 0; f < 2; f++) {
            uint32_t off = (uint32_t)((warp_m * 32 + f * 16 + rA) * 64 + kb + bA);
            LDSM4(Af[f], bufb + AL_OFF + SW64(off));
        }
#pragma unroll
        for (int f = 0; f < 2; f++)
#pragma unroll
            for (int nf = 0; nf < 4; nf++)
                MMA(c[f][nf], Af[f], Bh[nf >> 1][(nf & 1) * 2], Bh[nf >> 1][(nf & 1) * 2 + 1]);
    }
}

// ---------------------------------------------------------------------------
// Kernel 0: reset cursors + zero output
// ---------------------------------------------------------------------------
__global__ void k_zero(float* __restrict__ out, int n_elems) {
    if (blockIdx.x == 0 && threadIdx.x < E_) g_cursor[threadIdx.x] = 0;
    int i = blockIdx.x * blockDim.x + threadIdx.x;
    int stride = gridDim.x * blockDim.x;
    float4 z = make_float4(0.f, 0.f, 0.f, 0.f);
    for (int idx = i; idx * 4 < n_elems; idx += stride)
        reinterpret_cast<float4*>(out)[idx] = z;
}

// ---------------------------------------------------------------------------
// Kernel 1: fp32 -> bf16 hi/lo split, 2-wide ILP
// ---------------------------------------------------------------------------
static __device__ __forceinline__ void split4(float4 v, uint2& H, uint2& L) {
    __nv_bfloat16 hx = __float2bfloat16(v.x), hy = __float2bfloat16(v.y);
    __nv_bfloat16 hz = __float2bfloat16(v.z), hw = __float2bfloat16(v.w);
    float lx = v.x - __bfloat162float(hx), ly = v.y - __bfloat162float(hy);
    float lz = v.z - __bfloat162float(hz), lw = v.w - __bfloat162float(hw);
    H.x = ((uint32_t)__bfloat16_as_ushort(hy) << 16) | __bfloat16_as_ushort(hx);
    H.y = ((uint32_t)__bfloat16_as_ushort(hw) << 16) | __bfloat16_as_ushort(hz);
    __nv_bfloat16 ax = __float2bfloat16(lx), ay = __float2bfloat16(ly);
    __nv_bfloat16 az = __float2bfloat16(lz), aw = __float2bfloat16(lw);
    L.x = ((uint32_t)__bfloat16_as_ushort(ay) << 16) | __bfloat16_as_ushort(ax);
    L.y = ((uint32_t)__bfloat16_as_ushort(aw) << 16) | __bfloat16_as_ushort(az);
}

__global__ void k_split(const float4* __restrict__ src,
                        uint2* __restrict__ hi, uint2* __restrict__ lo, int n4) {
    int i = blockIdx.x * blockDim.x + threadIdx.x;
    int stride = gridDim.x * blockDim.x;
    for (int idx = i; idx < n4; idx += 2 * stride) {
        int idx2 = idx + stride;
        float4 v0 = src[idx];
        float4 v1 = (idx2 < n4) ? src[idx2] : v0;
        uint2 H0, L0, H1, L1;
        split4(v0, H0, L0);
        split4(v1, H1, L1);
        hi[idx] = H0; lo[idx] = L0;
        if (idx2 < n4) { hi[idx2] = H1; lo[idx2] = L1; }
    }
}

// ---------------------------------------------------------------------------
// Kernel 2: gating (one warp per token)
// ---------------------------------------------------------------------------
__global__ void k_gate(const float* __restrict__ x, const float* __restrict__ gw) {
    int warp = threadIdx.x >> 5;
    int lane = threadIdx.x & 31;
    int t = blockIdx.x * 8 + warp;
    const float* xr = x + (size_t)t * D_;

    float xv[32];
#pragma unroll
    for (int i = 0; i < 32; i++) xv[i] = xr[i * 32 + lane];

    float logit[E_];
#pragma unroll
    for (int e = 0; e < E_; e++) {
        const float* wr = gw + e * D_;
        float acc = 0.f;
#pragma unroll
        for (int i = 0; i < 32; i++) acc = fmaf(xv[i], wr[i * 32 + lane], acc);
#pragma unroll
        for (int s = 16; s > 0; s >>= 1) acc += __shfl_xor_sync(0xffffffffu, acc, s);
        logit[e] = acc;
    }

    if (lane == 0) {
        int e0 = 0;
#pragma unroll
        for (int e = 1; e < E_; e++) if (logit[e] > logit[e0]) e0 = e;
        int e1 = (e0 == 0) ? 1 : 0;
#pragma unroll
        for (int e = 0; e < E_; e++) if (e != e0 && logit[e] > logit[e1]) e1 = e;

        float m  = logit[e0];
        float x0 = expf(logit[e0] - m);
        float x1 = expf(logit[e1] - m);
        float inv = 1.f / (x0 + x1);

        int p0 = atomicAdd(&g_cursor[e0], 1);
        g_tok[e0 * T_ + p0] = t;  g_wgt[e0 * T_ + p0] = x0 * inv;
        int p1 = atomicAdd(&g_cursor[e1], 1);
        g_tok[e1 * T_ + p1] = t;  g_wgt[e1 * T_ + p1] = x1 * inv;
    }
}

__global__ void k_prefix() {
    if (threadIdx.x == 0) {
        int b = 0;
        for (int e = 0; e < E_; e++) { g_base[e] = b; b += g_cursor[e]; }
    }
}

// ---------------------------------------------------------------------------
// Kernel 3: GEMM1  H = gelu(gather(X) @ Wfc[e]^T + b)  (bf16 HMMA, 3-term)
// grid (F/128, T/128, E), 512 threads, 3-stage pipeline
// ---------------------------------------------------------------------------
__global__ void __launch_bounds__(NTH, 1)
k_fc_mma(const float* __restrict__ bfc) {
    int e = blockIdx.z;
    int cnt = g_cursor[e];
    int row0 = blockIdx.y * BM;
    if (row0 >= cnt) return;
    int n0 = blockIdx.x * BN;

    extern __shared__ __align__(1024) char smem[];
    __shared__ int s_toff[BM];
    int tid = threadIdx.x, wid = tid >> 5, lane = tid & 31;
    uint32_t sb = smem_u32(smem);

    if (tid < BM) s_toff[tid] = g_tok[e * T_ + min(row0 + tid, cnt - 1)] * D_;
    __syncthreads();

    int warp_m = wid >> 2, warp_n = wid & 3;   // 4 x 4 warps, tile 32x32
    int g = lane >> 3, l8 = lane & 7;
    int rA = (g & 1) * 8 + l8, bA = (g >> 1) * 16;
    int rB = (g >> 1) * 8 + l8, bB = (g & 1) * 16;

    // copy coords: per stage array = 512 16B units; 1 per thread
    int ur = tid >> 2, uc = tid & 3;

    const __nv_bfloat16* wh = g_wfh + (size_t)e * F_ * D_;
    const __nv_bfloat16* wl = g_wfl + (size_t)e * F_ * D_;

#define FC_ISSUE(ci, sg)                                                        \
    {                                                                           \
        uint32_t bufb = sb + (sg) * STAGE_B;                                    \
        int k0 = (ci) * KC;                                                     \
        uint32_t dst = SW64((uint32_t)(ur * 64 + uc * 16));                     \
        size_t ao = (size_t)s_toff[ur] + k0 + uc * 8;                           \
        size_t bo = (size_t)(n0 + ur) * D_ + k0 + uc * 8;                       \
        CPA(bufb + AH_OFF + dst, g_xh + ao);                                    \
        CPA(bufb + AL_OFF + dst, g_xl + ao);                                    \
        CPA(bufb + BH_OFF + dst, wh + bo);                                      \
        CPA(bufb + BL_OFF + dst, wl + bo);                                      \
        CPA_COMMIT();                                                           \
    }

    FC_ISSUE(0, 0);
    FC_ISSUE(1, 1);

    float c[2][4][4];
#pragma unroll
    for (int f = 0; f < 2; f++)
#pragma unroll
        for (int nf = 0; nf < 4; nf++)
#pragma unroll
            for (int q = 0; q < 4; q++) c[f][nf][q] = 0.f;

    const int KCH = D_ / KC;   // 32
    int stage = 0;
    for (int i = 0; i < KCH; i++) {
        if (i < KCH - 1) asm volatile("cp.async.wait_group 1;" ::: "memory");
        else             asm volatile("cp.async.wait_group 0;" ::: "memory");
        __syncthreads();
        if (i + 2 < KCH) {
            int sg = stage + 2; if (sg >= NSTAGE) sg -= NSTAGE;
            FC_ISSUE(i + 2, sg);
        }
        mma_chunk(sb + stage * STAGE_B, warp_m, warp_n, rA, bA, rB, bB, c);
        if (++stage == NSTAGE) stage = 0;
    }
#undef FC_ISSUE

    // Epilogue: bias + gelu -> split bf16 hi/lo into g_hh/g_hl
    int qr = lane >> 2, qc = (lane & 3) * 2;
    int hbase = g_base[e];
#pragma unroll
    for (int f = 0; f < 2; f++) {
#pragma unroll
        for (int pr = 0; pr < 2; pr++) {
            int r = row0 + warp_m * 32 + f * 16 + qr + pr * 8;
            if (r >= cnt) continue;
            size_t hr = (size_t)(hbase + r);
#pragma unroll
            for (int nf = 0; nf < 4; nf++) {
                int n = n0 + warp_n * 32 + nf * 8 + qc;
                float v0 = ngelu(c[f][nf][pr * 2 + 0] + bfc[e * F_ + n]);
                float v1 = ngelu(c[f][nf][pr * 2 + 1] + bfc[e * F_ + n + 1]);
                __nv_bfloat16 h0 = __float2bfloat16(v0), h1 = __float2bfloat16(v1);
                float l0 = v0 - __bfloat162float(h0), l1 = v1 - __bfloat162float(h1);
                __nv_bfloat16 a0 = __float2bfloat16(l0), a1 = __float2bfloat16(l1);
                *reinterpret_cast<uint32_t*>(g_hh + hr * F_ + n) =
                    ((uint32_t)__bfloat16_as_ushort(h1) << 16) | __bfloat16_as_ushort(h0);
                *reinterpret_cast<uint32_t*>(g_hl + hr * F_ + n) =
                    ((uint32_t)__bfloat16_as_ushort(a1) << 16) | __bfloat16_as_ushort(a0);
            }
        }
    }
}

// ---------------------------------------------------------------------------
// Kernel 4: GEMM2  out[token] += w * (H @ Wproj[e]^T + b)
// grid (D/128, T/128, E), 512 threads
// ---------------------------------------------------------------------------
__global__ void __launch_bounds__(NTH, 1)
k_proj_mma(const float* __restrict__ bpj, float* __restrict__ out) {
    int e = blockIdx.z;
    int cnt = g_cursor[e];
    int row0 = blockIdx.y * BM;
    if (row0 >= cnt) return;
    int n0 = blockIdx.x * BN;

    extern __shared__ __align__(1024) char smem[];
    __shared__ int   s_hrow[BM];
    __shared__ int   s_tok[BM];
    __shared__ float s_wgt[BM];
    int tid = threadIdx.x, wid = tid >> 5, lane = tid & 31;
    uint32_t sb = smem_u32(smem);

    if (tid < BM) {
        int r = min(row0 + tid, cnt - 1);
        s_hrow[tid] = g_base[e] + r;
        s_tok[tid]  = g_tok[e * T_ + r];
        s_wgt[tid]  = g_wgt[e * T_ + r];
    }
    __syncthreads();

    int warp_m = wid >> 2, warp_n = wid & 3;
    int g = lane >> 3, l8 = lane & 7;
    int rA = (g & 1) * 8 + l8, bA = (g >> 1) * 16;
    int rB = (g >> 1) * 8 + l8, bB = (g & 1) * 16;

    int ur = tid >> 2, uc = tid & 3;

    const __nv_bfloat16* wh = g_wph + (size_t)e * D_ * F_;
    const __nv_bfloat16* wl = g_wpl + (size_t)e * D_ * F_;

#define PJ_ISSUE(ci, sg)                                                        \
    {                                                                           \
        uint32_t bufb = sb + (sg) * STAGE_B;                                    \
        int k0 = (ci) * KC;                                                     \
        uint32_t dst = SW64((uint32_t)(ur * 64 + uc * 16));                     \
        size_t ao = (size_t)s_hrow[ur] * F_ + k0 + uc * 8;                      \
        size_t bo = (size_t)(n0 + ur) * F_ + k0 + uc * 8;                       \
        CPA(bufb + AH_OFF + dst, g_hh + ao);                                    \
        CPA(bufb + AL_OFF + dst, g_hl + ao);                                    \
        CPA(bufb + BH_OFF + dst, wh + bo);                                      \
        CPA(bufb + BL_OFF + dst, wl + bo);                                      \
        CPA_COMMIT();                                                           \
    }

    PJ_ISSUE(0, 0);
    PJ_ISSUE(1, 1);

    float c[2][4][4];
#pragma unroll
    for (int f = 0; f < 2; f++)
#pragma unroll
        for (int nf = 0; nf < 4; nf++)
#pragma unroll
            for (int q = 0; q < 4; q++) c[f][nf][q] = 0.f;

    const int KCH = F_ / KC;   // 128
    int stage = 0;
    for (int i = 0; i < KCH; i++) {
        if (i < KCH - 1) asm volatile("cp.async.wait_group 1;" ::: "memory");
        else             asm volatile("cp.async.wait_group 0;" ::: "memory");
        __syncthreads();
        if (i + 2 < KCH) {
            int sg = stage + 2; if (sg >= NSTAGE) sg -= NSTAGE;
            PJ_ISSUE(i + 2, sg);
        }
        mma_chunk(sb + stage * STAGE_B, warp_m, warp_n, rA, bA, rB, bB, c);
        if (++stage == NSTAGE) stage = 0;
    }
#undef PJ_ISSUE

    // Epilogue: (acc + bias) * routing weight, atomic scatter (2 adds/elem total)
    int qr = lane >> 2, qc = (lane & 3) * 2;
#pragma unroll
    for (int f = 0; f < 2; f++) {
#pragma unroll
        for (int pr = 0; pr < 2; pr++) {
            int rl = warp_m * 32 + f * 16 + qr + pr * 8;
            int r = row0 + rl;
            if (r >= cnt) continue;
            int   token = s_tok[rl];
            float w     = s_wgt[rl];
            float* orow = out + (size_t)token * D_;
#pragma unroll
            for (int nf = 0; nf < 4; nf++) {
                int n = n0 + warp_n * 32 + nf * 8 + qc;
                atomicAdd(orow + n,     (c[f][nf][pr * 2 + 0] + bpj[e * D_ + n])     * w);
                atomicAdd(orow + n + 1, (c[f][nf][pr * 2 + 1] + bpj[e * D_ + n + 1]) * w);
            }
        }
    }
}

// ---------------------------------------------------------------------------
// Launch. Order chosen so ncu (-s 5 -c 1) captures k_fc_mma (launch index 5).
// ---------------------------------------------------------------------------
extern "C" void kernel_launch(void* const* d_in, const int* in_sizes, int n_in,
                              void* d_out, int out_size) {
    const float* x   = (const float*)d_in[0];
    const float* gw  = (const float*)d_in[1];
    const float* wfc = (const float*)d_in[2];
    const float* bfc = (const float*)d_in[3];
    const float* wpj = (const float*)d_in[4];
    const float* bpj = (const float*)d_in[5];
    float* out = (float*)d_out;

    cudaFuncSetAttribute(k_fc_mma,   cudaFuncAttributeMaxDynamicSharedMemorySize, SMEM_DYN);
    cudaFuncSetAttribute(k_proj_mma, cudaFuncAttributeMaxDynamicSharedMemorySize, SMEM_DYN);

    __nv_bfloat16 *xh, *xl, *wfh, *wfl, *wph, *wpl;
    cudaGetSymbolAddress((void**)&xh,  g_xh);
    cudaGetSymbolAddress((void**)&xl,  g_xl);
    cudaGetSymbolAddress((void**)&wfh, g_wfh);
    cudaGetSymbolAddress((void**)&wfl, g_wfl);
    cudaGetSymbolAddress((void**)&wph, g_wph);
    cudaGetSymbolAddress((void**)&wpl, g_wpl);

    k_zero  <<<2048, 256>>>(out, out_size);                                           // 0
    k_gate  <<<T_ / 8, 256>>>(x, gw);                                                 // 1
    k_prefix<<<1, 32>>>();                                                            // 2
    k_split <<<4096, 256>>>((const float4*)x,   (uint2*)xh,  (uint2*)xl,  T_ * D_ / 4);        // 3
    k_split <<<8192, 256>>>((const float4*)wfc, (uint2*)wfh, (uint2*)wfl, E_ * F_ * D_ / 4);   // 4
    k_fc_mma  <<<dim3(F_ / BN, T_ / BM, E_), NTH, SMEM_DYN>>>(bfc);                   // 5 <- ncu
    k_split <<<8192, 256>>>((const float4*)wpj, (uint2*)wph, (uint2*)wpl, E_ * D_ * F_ / 4);   // 6
    k_proj_mma<<<dim3(D_ / BN, T_ / BM, E_), NTH, SMEM_DYN>>>(bpj, out);              // 7
}

// round 8
// speedup vs baseline: 1.0268x; 1.0268x over previous
#include <cuda_runtime.h>
#include <cuda_bf16.h>
#include <math.h>
#include <stdint.h>

// Problem constants
#define E_  8
#define D_  1024
#define F_  4096
#define T_  8192
#define TK_ (T_ * 2)

// GEMM tiling: 128x128 block, 256 threads (8 warps), warp tile 64x32,
// KC=32 chunk (64B bf16 rows, SW64 swizzle), 3-stage cp.async pipeline.
#define BM 128
#define BN 128
#define KC 32
#define NTH 256
#define AH_OFF 0
#define AL_OFF 8192
#define BH_OFF 16384
#define BL_OFF 24576
#define STAGE_B 32768
#define NSTAGE 3
#define SMEM_DYN (NSTAGE * STAGE_B)   // 96 KB

// ---------------------------------------------------------------------------
// Device scratch (static: no allocations allowed)
// ---------------------------------------------------------------------------
__device__ __nv_bfloat16 g_xh[(size_t)T_ * D_];
__device__ __nv_bfloat16 g_xl[(size_t)T_ * D_];
__device__ __nv_bfloat16 g_wfh[(size_t)E_ * F_ * D_];
__device__ __nv_bfloat16 g_wfl[(size_t)E_ * F_ * D_];
__device__ __nv_bfloat16 g_wph[(size_t)E_ * D_ * F_];
__device__ __nv_bfloat16 g_wpl[(size_t)E_ * D_ * F_];
__device__ __nv_bfloat16 g_hh[(size_t)TK_ * F_];
__device__ __nv_bfloat16 g_hl[(size_t)TK_ * F_];
__device__ int   g_tok[E_ * T_];
__device__ float g_wgt[E_ * T_];
__device__ int   g_cursor[E_];

// ---------------------------------------------------------------------------
// Helpers
// ---------------------------------------------------------------------------
static __device__ __forceinline__ uint32_t smem_u32(const void* p) {
    uint32_t a;
    asm("{ .reg .u64 t; cvta.to.shared.u64 t, %1; cvt.u32.u64 %0, t; }"
        : "=r"(a) : "l"(p));
    return a;
}

// 64B-row swizzle: XOR 16B-unit bits [4:5] with row bits 1-2 (o bits [7:8]).
#define SW64(o) ((o) ^ (((o) >> 3) & 0x30))

#define CPA(dst, src) \
    asm volatile("cp.async.cg.shared.global [%0], [%1], 16;" \
                 :: "r"(dst), "l"(src) : "memory")
#define CPA_COMMIT() asm volatile("cp.async.commit_group;" ::: "memory")

#define LDSM4(r, addr) \
    asm volatile("ldmatrix.sync.aligned.m8n8.x4.shared.b16 {%0,%1,%2,%3}, [%4];" \
                 : "=r"((r)[0]), "=r"((r)[1]), "=r"((r)[2]), "=r"((r)[3]) \
                 : "r"(addr))

#define MMA(cd, a, b0, b1) \
    asm volatile("mma.sync.aligned.m16n8k16.row.col.f32.bf16.bf16.f32 " \
                 "{%0,%1,%2,%3}, {%4,%5,%6,%7}, {%8,%9}, {%0,%1,%2,%3};" \
                 : "+f"((cd)[0]), "+f"((cd)[1]), "+f"((cd)[2]), "+f"((cd)[3]) \
                 : "r"((a)[0]), "r"((a)[1]), "r"((a)[2]), "r"((a)[3]), \
                   "r"(b0), "r"(b1))

static __device__ __forceinline__ float ngelu(float v) {
    float u = 0.7978845608028654f * (v + 0.044715f * v * v * v);
    return 0.5f * v * (1.0f + tanhf(u));
}

// Local prefix of expert bucket bases (gate finished before GEMM launches)
static __device__ __forceinline__ int expert_base(int e) {
    int b = 0;
#pragma unroll
    for (int j = 0; j < E_; j++) if (j < e) b += g_cursor[j];
    return b;
}

// One K=32 chunk of the 3-term split MMA (Ah*Bh + Ah*Bl + Al*Bh).
// Warp tile 64(M) x 32(N): 4 M-frags, 4 N-frags, 64 accumulators.
static __device__ __forceinline__ void mma_chunk(
    uint32_t bufb, int warp_m, int warp_n,
    int rA, int bA, int rB, int bB, float (&c)[4][4][4]) {
#pragma unroll
    for (int ks = 0; ks < 2; ks++) {
        int kb = ks * 32;
        uint32_t Af[4][4], Bh[2][4], Bl[2][4];
#pragma unroll
        for (int f = 0; f < 4; f++) {
            uint32_t off = (uint32_t)((warp_m * 64 + f * 16 + rA) * 64 + kb + bA);
            LDSM4(Af[f], bufb + AH_OFF + SW64(off));
        }
#pragma unroll
        for (int p = 0; p < 2; p++) {
            uint32_t off = (uint32_t)((warp_n * 32 + p * 16 + rB) * 64 + kb + bB);
            LDSM4(Bh[p], bufb + BH_OFF + SW64(off));
        }
#pragma unroll
        for (int p = 0; p < 2; p++) {
            uint32_t off = (uint32_t)((warp_n * 32 + p * 16 + rB) * 64 + kb + bB);
            LDSM4(Bl[p], bufb + BL_OFF + SW64(off));
        }
#pragma unroll
        for (int f = 0; f < 4; f++)
#pragma unroll
            for (int nf = 0; nf < 4; nf++)
                MMA(c[f][nf], Af[f], Bh[nf >> 1][(nf & 1) * 2], Bh[nf >> 1][(nf & 1) * 2 + 1]);
#pragma unroll
        for (int f = 0; f < 4; f++)
#pragma unroll
            for (int nf = 0; nf < 4; nf++)
                MMA(c[f][nf], Af[f], Bl[nf >> 1][(nf & 1) * 2], Bl[nf >> 1][(nf & 1) * 2 + 1]);
        // reload A with lo part (reuses Af registers)
#pragma unroll
        for (int f = 0; f < 4; f++) {
            uint32_t off = (uint32_t)((warp_m * 64 + f * 16 + rA) * 64 + kb + bA);
            LDSM4(Af[f], bufb + AL_OFF + SW64(off));
        }
#pragma unroll
        for (int f = 0; f < 4; f++)
#pragma unroll
            for (int nf = 0; nf < 4; nf++)
                MMA(c[f][nf], Af[f], Bh[nf >> 1][(nf & 1) * 2], Bh[nf >> 1][(nf & 1) * 2 + 1]);
    }
}

// ---------------------------------------------------------------------------
// Kernel 0: reset cursors + zero output
// ---------------------------------------------------------------------------
__global__ void k_zero(float* __restrict__ out, int n_elems) {
    if (blockIdx.x == 0 && threadIdx.x < E_) g_cursor[threadIdx.x] = 0;
    int i = blockIdx.x * blockDim.x + threadIdx.x;
    int stride = gridDim.x * blockDim.x;
    float4 z = make_float4(0.f, 0.f, 0.f, 0.f);
    for (int idx = i; idx * 4 < n_elems; idx += stride)
        reinterpret_cast<float4*>(out)[idx] = z;
}

// ---------------------------------------------------------------------------
// Kernel 1: gating (one warp per token)
// ---------------------------------------------------------------------------
__global__ void k_gate(const float* __restrict__ x, const float* __restrict__ gw) {
    int warp = threadIdx.x >> 5;
    int lane = threadIdx.x & 31;
    int t = blockIdx.x * 8 + warp;
    const float* xr = x + (size_t)t * D_;

    float xv[32];
#pragma unroll
    for (int i = 0; i < 32; i++) xv[i] = xr[i * 32 + lane];

    float logit[E_];
#pragma unroll
    for (int e = 0; e < E_; e++) {
        const float* wr = gw + e * D_;
        float acc = 0.f;
#pragma unroll
        for (int i = 0; i < 32; i++) acc = fmaf(xv[i], wr[i * 32 + lane], acc);
#pragma unroll
        for (int s = 16; s > 0; s >>= 1) acc += __shfl_xor_sync(0xffffffffu, acc, s);
        logit[e] = acc;
    }

    if (lane == 0) {
        int e0 = 0;
#pragma unroll
        for (int e = 1; e < E_; e++) if (logit[e] > logit[e0]) e0 = e;
        int e1 = (e0 == 0) ? 1 : 0;
#pragma unroll
        for (int e = 0; e < E_; e++) if (e != e0 && logit[e] > logit[e1]) e1 = e;

        float m  = logit[e0];
        float x0 = expf(logit[e0] - m);
        float x1 = expf(logit[e1] - m);
        float inv = 1.f / (x0 + x1);

        int p0 = atomicAdd(&g_cursor[e0], 1);
        g_tok[e0 * T_ + p0] = t;  g_wgt[e0 * T_ + p0] = x0 * inv;
        int p1 = atomicAdd(&g_cursor[e1], 1);
        g_tok[e1 * T_ + p1] = t;  g_wgt[e1 * T_ + p1] = x1 * inv;
    }
}

// ---------------------------------------------------------------------------
// Kernel 2: fused fp32 -> bf16 hi/lo split of x, wfc, wpj (one launch).
// ALU-thin: packed cvt.rn.bf16x2 + bit-mask reconstruction of hi.
// ---------------------------------------------------------------------------
#define N4_X (T_ * D_ / 4)
#define N4_W (E_ * F_ * D_ / 4)

static __device__ __forceinline__ void split4f(float4 v, uint2& H, uint2& L) {
    uint32_t h01, h23;
    asm("cvt.rn.bf16x2.f32 %0, %1, %2;" : "=r"(h01) : "f"(v.y), "f"(v.x));
    asm("cvt.rn.bf16x2.f32 %0, %1, %2;" : "=r"(h23) : "f"(v.w), "f"(v.z));
    float r0 = __uint_as_float(h01 << 16);
    float r1 = __uint_as_float(h01 & 0xFFFF0000u);
    float r2 = __uint_as_float(h23 << 16);
    float r3 = __uint_as_float(h23 & 0xFFFF0000u);
    uint32_t l01, l23;
    asm("cvt.rn.bf16x2.f32 %0, %1, %2;" : "=r"(l01) : "f"(v.y - r1), "f"(v.x - r0));
    asm("cvt.rn.bf16x2.f32 %0, %1, %2;" : "=r"(l23) : "f"(v.w - r3), "f"(v.z - r2));
    H.x = h01; H.y = h23; L.x = l01; L.y = l23;
}

__global__ void k_split3(const float4* __restrict__ x,
                         const float4* __restrict__ wfc,
                         const float4* __restrict__ wpj) {
    const int total = N4_X + 2 * N4_W;
    int i = blockIdx.x * blockDim.x + threadIdx.x;
    int stride = gridDim.x * blockDim.x;
    for (int idx = i; idx < total; idx += stride) {
        const float4* s; uint2 *H, *L; int k;
        if (idx < N4_X) {
            s = x; k = idx;
            H = (uint2*)g_xh; L = (uint2*)g_xl;
        } else if (idx < N4_X + N4_W) {
            s = wfc; k = idx - N4_X;
            H = (uint2*)g_wfh; L = (uint2*)g_wfl;
        } else {
            s = wpj; k = idx - N4_X - N4_W;
            H = (uint2*)g_wph; L = (uint2*)g_wpl;
        }
        uint2 Hv, Lv;
        split4f(s[k], Hv, Lv);
        H[k] = Hv; L[k] = Lv;
    }
}

// ---------------------------------------------------------------------------
// Kernel 3: GEMM1  H = gelu(gather(X) @ Wfc[e]^T + b)  (bf16 HMMA, 3-term)
// grid (T/128, F/128, E)  -- row-tiles FASTEST for L2 weight reuse
// ---------------------------------------------------------------------------
__global__ void __launch_bounds__(NTH, 1)
k_fc_mma(const float* __restrict__ bfc) {
    int e = blockIdx.z;
    int cnt = g_cursor[e];
    int row0 = blockIdx.x * BM;
    if (row0 >= cnt) return;
    int n0 = blockIdx.y * BN;
    int hbase = expert_base(e);

    extern __shared__ __align__(1024) char smem[];
    __shared__ int s_toff[BM];
    int tid = threadIdx.x, wid = tid >> 5, lane = tid & 31;
    uint32_t sb = smem_u32(smem);

    if (tid < BM) s_toff[tid] = g_tok[e * T_ + min(row0 + tid, cnt - 1)] * D_;
    __syncthreads();

    int warp_m = wid >> 2, warp_n = wid & 3;   // 2 x 4 warps, tile 64x32
    int g = lane >> 3, l8 = lane & 7;
    int rA = (g & 1) * 8 + l8, bA = (g >> 1) * 16;
    int rB = (g >> 1) * 8 + l8, bB = (g & 1) * 16;

    // copy coords: per stage array = 512 16B units; 2 per thread
    int ur[2], uc[2];
#pragma unroll
    for (int j = 0; j < 2; j++) { int u = tid + j * NTH; ur[j] = u >> 2; uc[j] = u & 3; }

    const __nv_bfloat16* wh = g_wfh + (size_t)e * F_ * D_;
    const __nv_bfloat16* wl = g_wfl + (size_t)e * F_ * D_;

#define FC_ISSUE(ci, sg)                                                        \
    {                                                                           \
        uint32_t bufb = sb + (sg) * STAGE_B;                                    \
        int k0 = (ci) * KC;                                                     \
        _Pragma("unroll")                                                       \
        for (int j = 0; j < 2; j++) {                                           \
            uint32_t dst = SW64((uint32_t)(ur[j] * 64 + uc[j] * 16));           \
            size_t ao = (size_t)s_toff[ur[j]] + k0 + uc[j] * 8;                 \
            size_t bo = (size_t)(n0 + ur[j]) * D_ + k0 + uc[j] * 8;             \
            CPA(bufb + AH_OFF + dst, g_xh + ao);                                \
            CPA(bufb + AL_OFF + dst, g_xl + ao);                                \
            CPA(bufb + BH_OFF + dst, wh + bo);                                  \
            CPA(bufb + BL_OFF + dst, wl + bo);                                  \
        }                                                                       \
        CPA_COMMIT();                                                           \
    }

    FC_ISSUE(0, 0);
    FC_ISSUE(1, 1);

    float c[4][4][4];
#pragma unroll
    for (int f = 0; f < 4; f++)
#pragma unroll
        for (int nf = 0; nf < 4; nf++)
#pragma unroll
            for (int q = 0; q < 4; q++) c[f][nf][q] = 0.f;

    const int KCH = D_ / KC;   // 32
    int stage = 0;
    for (int i = 0; i < KCH; i++) {
        if (i < KCH - 1) asm volatile("cp.async.wait_group 1;" ::: "memory");
        else             asm volatile("cp.async.wait_group 0;" ::: "memory");
        __syncthreads();
        if (i + 2 < KCH) {
            int sg = stage + 2; if (sg >= NSTAGE) sg -= NSTAGE;
            FC_ISSUE(i + 2, sg);
        }
        mma_chunk(sb + stage * STAGE_B, warp_m, warp_n, rA, bA, rB, bB, c);
        if (++stage == NSTAGE) stage = 0;
    }
#undef FC_ISSUE

    // Epilogue: bias + gelu -> split bf16 hi/lo into g_hh/g_hl
    int qr = lane >> 2, qc = (lane & 3) * 2;
#pragma unroll
    for (int f = 0; f < 4; f++) {
#pragma unroll
        for (int pr = 0; pr < 2; pr++) {
            int r = row0 + warp_m * 64 + f * 16 + qr + pr * 8;
            if (r >= cnt) continue;
            size_t hr = (size_t)(hbase + r);
#pragma unroll
            for (int nf = 0; nf < 4; nf++) {
                int n = n0 + warp_n * 32 + nf * 8 + qc;
                float v0 = ngelu(c[f][nf][pr * 2 + 0] + bfc[e * F_ + n]);
                float v1 = ngelu(c[f][nf][pr * 2 + 1] + bfc[e * F_ + n + 1]);
                __nv_bfloat16 h0 = __float2bfloat16(v0), h1 = __float2bfloat16(v1);
                float l0 = v0 - __bfloat162float(h0), l1 = v1 - __bfloat162float(h1);
                __nv_bfloat16 a0 = __float2bfloat16(l0), a1 = __float2bfloat16(l1);
                *reinterpret_cast<uint32_t*>(g_hh + hr * F_ + n) =
                    ((uint32_t)__bfloat16_as_ushort(h1) << 16) | __bfloat16_as_ushort(h0);
                *reinterpret_cast<uint32_t*>(g_hl + hr * F_ + n) =
                    ((uint32_t)__bfloat16_as_ushort(a1) << 16) | __bfloat16_as_ushort(a0);
            }
        }
    }
}

// ---------------------------------------------------------------------------
// Kernel 4: GEMM2  out[token] += w * (H @ Wproj[e]^T + b)
// grid (T/128, D/128, E)  -- row-tiles FASTEST for L2 weight reuse
// ---------------------------------------------------------------------------
__global__ void __launch_bounds__(NTH, 1)
k_proj_mma(const float* __restrict__ bpj, float* __restrict__ out) {
    int e = blockIdx.z;
    int cnt = g_cursor[e];
    int row0 = blockIdx.x * BM;
    if (row0 >= cnt) return;
    int n0 = blockIdx.y * BN;
    int hbase = expert_base(e);

    extern __shared__ __align__(1024) char smem[];
    __shared__ int   s_hrow[BM];
    __shared__ int   s_tok[BM];
    __shared__ float s_wgt[BM];
    int tid = threadIdx.x, wid = tid >> 5, lane = tid & 31;
    uint32_t sb = smem_u32(smem);

    if (tid < BM) {
        int r = min(row0 + tid, cnt - 1);
        s_hrow[tid] = hbase + r;
        s_tok[tid]  = g_tok[e * T_ + r];
        s_wgt[tid]  = g_wgt[e * T_ + r];
    }
    __syncthreads();

    int warp_m = wid >> 2, warp_n = wid & 3;
    int g = lane >> 3, l8 = lane & 7;
    int rA = (g & 1) * 8 + l8, bA = (g >> 1) * 16;
    int rB = (g >> 1) * 8 + l8, bB = (g & 1) * 16;

    int ur[2], uc[2];
#pragma unroll
    for (int j = 0; j < 2; j++) { int u = tid + j * NTH; ur[j] = u >> 2; uc[j] = u & 3; }

    const __nv_bfloat16* wh = g_wph + (size_t)e * D_ * F_;
    const __nv_bfloat16* wl = g_wpl + (size_t)e * D_ * F_;

#define PJ_ISSUE(ci, sg)                                                        \
    {                                                                           \
        uint32_t bufb = sb + (sg) * STAGE_B;                                    \
        int k0 = (ci) * KC;                                                     \
        _Pragma("unroll")                                                       \
        for (int j = 0; j < 2; j++) {                                           \
            uint32_t dst = SW64((uint32_t)(ur[j] * 64 + uc[j] * 16));           \
            size_t ao = (size_t)s_hrow[ur[j]] * F_ + k0 + uc[j] * 8;            \
            size_t bo = (size_t)(n0 + ur[j]) * F_ + k0 + uc[j] * 8;             \
            CPA(bufb + AH_OFF + dst, g_hh + ao);                                \
            CPA(bufb + AL_OFF + dst, g_hl + ao);                                \
            CPA(bufb + BH_OFF + dst, wh + bo);                                  \
            CPA(bufb + BL_OFF + dst, wl + bo);                                  \
        }                                                                       \
        CPA_COMMIT();                                                           \
    }

    PJ_ISSUE(0, 0);
    PJ_ISSUE(1, 1);

    float c[4][4][4];
#pragma unroll
    for (int f = 0; f < 4; f++)
#pragma unroll
        for (int nf = 0; nf < 4; nf++)
#pragma unroll
            for (int q = 0; q < 4; q++) c[f][nf][q] = 0.f;

    const int KCH = F_ / KC;   // 128
    int stage = 0;
    for (int i = 0; i < KCH; i++) {
        if (i < KCH - 1) asm volatile("cp.async.wait_group 1;" ::: "memory");
        else             asm volatile("cp.async.wait_group 0;" ::: "memory");
        __syncthreads();
        if (i + 2 < KCH) {
            int sg = stage + 2; if (sg >= NSTAGE) sg -= NSTAGE;
            PJ_ISSUE(i + 2, sg);
        }
        mma_chunk(sb + stage * STAGE_B, warp_m, warp_n, rA, bA, rB, bB, c);
        if (++stage == NSTAGE) stage = 0;
    }
#undef PJ_ISSUE

    // Epilogue: (acc + bias) * routing weight, atomic scatter (2 adds/elem total)
    int qr = lane >> 2, qc = (lane & 3) * 2;
#pragma unroll
    for (int f = 0; f < 4; f++) {
#pragma unroll
        for (int pr = 0; pr < 2; pr++) {
            int rl = warp_m * 64 + f * 16 + qr + pr * 8;
            int r = row0 + rl;
            if (r >= cnt) continue;
            int   token = s_tok[rl];
            float w     = s_wgt[rl];
            float* orow = out + (size_t)token * D_;
#pragma unroll
            for (int nf = 0; nf < 4; nf++) {
                int n = n0 + warp_n * 32 + nf * 8 + qc;
                atomicAdd(orow + n,     (c[f][nf][pr * 2 + 0] + bpj[e * D_ + n])     * w);
                atomicAdd(orow + n + 1, (c[f][nf][pr * 2 + 1] + bpj[e * D_ + n + 1]) * w);
            }
        }
    }
}

// ---------------------------------------------------------------------------
// Launch: 5 launches; k_fc_mma at index 3 (== observed ncu capture slot).
// ---------------------------------------------------------------------------
extern "C" void kernel_launch(void* const* d_in, const int* in_sizes, int n_in,
                              void* d_out, int out_size) {
    const float* x   = (const float*)d_in[0];
    const float* gw  = (const float*)d_in[1];
    const float* wfc = (const float*)d_in[2];
    const float* bfc = (const float*)d_in[3];
    const float* wpj = (const float*)d_in[4];
    const float* bpj = (const float*)d_in[5];
    float* out = (float*)d_out;

    cudaFuncSetAttribute(k_fc_mma,   cudaFuncAttributeMaxDynamicSharedMemorySize, SMEM_DYN);
    cudaFuncSetAttribute(k_proj_mma, cudaFuncAttributeMaxDynamicSharedMemorySize, SMEM_DYN);

    k_zero  <<<2048, 256>>>(out, out_size);                                    // 0
    k_gate  <<<T_ / 8, 256>>>(x, gw);                                          // 1
    k_split3<<<8192, 256>>>((const float4*)x, (const float4*)wfc,
                            (const float4*)wpj);                               // 2
    k_fc_mma  <<<dim3(T_ / BM, F_ / BN, E_), NTH, SMEM_DYN>>>(bfc);            // 3 <- ncu
    k_proj_mma<<<dim3(T_ / BM, D_ / BN, E_), NTH, SMEM_DYN>>>(bpj, out);       // 4
}

// round 9
// speedup vs baseline: 1.1778x; 1.1471x over previous
#include <cuda_runtime.h>
#include <cuda_bf16.h>
#include <math.h>
#include <stdint.h>

// Problem constants
#define E_  8
#define D_  1024
#define F_  4096
#define T_  8192
#define TK_ (T_ * 2)

// GEMM tiling (R5-proven): 128x128 block, 256 threads, warp tile 64x32,
// KC=64 chunk (128B bf16 rows, SW128 swizzle), double-buffered cp.async.
#define BM 128
#define BN 128
#define KC 64
#define NTH 256
#define AH_OFF 0
#define AL_OFF 16384
#define BH_OFF 32768
#define BL_OFF 49152
#define BUF_B  65536
#define SMEM_DYN (2 * BUF_B)   // 128 KB

// ---------------------------------------------------------------------------
// Device scratch (static: no allocations allowed)
// ---------------------------------------------------------------------------
__device__ __nv_bfloat16 g_xh[(size_t)T_ * D_];
__device__ __nv_bfloat16 g_xl[(size_t)T_ * D_];
__device__ __nv_bfloat16 g_wfh[(size_t)E_ * F_ * D_];
__device__ __nv_bfloat16 g_wfl[(size_t)E_ * F_ * D_];
__device__ __nv_bfloat16 g_wph[(size_t)E_ * D_ * F_];
__device__ __nv_bfloat16 g_wpl[(size_t)E_ * D_ * F_];
__device__ __nv_bfloat16 g_hh[(size_t)TK_ * F_];
__device__ __nv_bfloat16 g_hl[(size_t)TK_ * F_];
__device__ int   g_tok[E_ * T_];
__device__ float g_wgt[E_ * T_];
__device__ int   g_cursor[E_];

// ---------------------------------------------------------------------------
// Helpers
// ---------------------------------------------------------------------------
static __device__ __forceinline__ uint32_t smem_u32(const void* p) {
    uint32_t a;
    asm("{ .reg .u64 t; cvta.to.shared.u64 t, %1; cvt.u32.u64 %0, t; }"
        : "=r"(a) : "l"(p));
    return a;
}

#define SW(o) ((o) ^ (((o) >> 3) & 0x70))

#define CPA(dst, src) \
    asm volatile("cp.async.cg.shared.global [%0], [%1], 16;" \
                 :: "r"(dst), "l"(src) : "memory")
#define CPA_COMMIT() asm volatile("cp.async.commit_group;" ::: "memory")

#define LDSM4(r, addr) \
    asm volatile("ldmatrix.sync.aligned.m8n8.x4.shared.b16 {%0,%1,%2,%3}, [%4];" \
                 : "=r"((r)[0]), "=r"((r)[1]), "=r"((r)[2]), "=r"((r)[3]) \
                 : "r"(addr))

#define MMA(cd, a, b0, b1) \
    asm volatile("mma.sync.aligned.m16n8k16.row.col.f32.bf16.bf16.f32 " \
                 "{%0,%1,%2,%3}, {%4,%5,%6,%7}, {%8,%9}, {%0,%1,%2,%3};" \
                 : "+f"((cd)[0]), "+f"((cd)[1]), "+f"((cd)[2]), "+f"((cd)[3]) \
                 : "r"((a)[0]), "r"((a)[1]), "r"((a)[2]), "r"((a)[3]), \
                   "r"(b0), "r"(b1))

static __device__ __forceinline__ float ngelu(float v) {
    float u = 0.7978845608028654f * (v + 0.044715f * v * v * v);
    return 0.5f * v * (1.0f + tanhf(u));
}

// Local prefix of expert bucket bases (gate finished before GEMM launches)
static __device__ __forceinline__ int expert_base(int e) {
    int b = 0;
#pragma unroll
    for (int j = 0; j < E_; j++) if (j < e) b += g_cursor[j];
    return b;
}

// Packed split of two fp32 into bf16-hi pair + bf16-lo pair
static __device__ __forceinline__ void split2(float v0, float v1,
                                              uint32_t& h01, uint32_t& l01) {
    asm("cvt.rn.bf16x2.f32 %0, %1, %2;" : "=r"(h01) : "f"(v1), "f"(v0));
    float r0 = __uint_as_float(h01 << 16);
    float r1 = __uint_as_float(h01 & 0xFFFF0000u);
    asm("cvt.rn.bf16x2.f32 %0, %1, %2;" : "=r"(l01) : "f"(v1 - r1), "f"(v0 - r0));
}

// One K=64 chunk of the 3-term split MMA (Ah*Bh + Ah*Bl + Al*Bh).
// Warp tile 64(M) x 32(N): 4 M-frags, 4 N-frags, 64 accumulators. (R5-proven)
static __device__ __forceinline__ void mma_chunk(
    uint32_t bufb, int warp_m, int warp_n,
    int rA, int bA, int rB, int bB, float (&c)[4][4][4]) {
#pragma unroll
    for (int ks = 0; ks < 4; ks++) {
        int kb = ks * 32;
        uint32_t Af[4][4], Bh[2][4], Bl[2][4];
#pragma unroll
        for (int f = 0; f < 4; f++) {
            uint32_t off = (uint32_t)((warp_m * 64 + f * 16 + rA) * 128 + kb + bA);
            LDSM4(Af[f], bufb + AH_OFF + SW(off));
        }
#pragma unroll
        for (int p = 0; p < 2; p++) {
            uint32_t off = (uint32_t)((warp_n * 32 + p * 16 + rB) * 128 + kb + bB);
            LDSM4(Bh[p], bufb + BH_OFF + SW(off));
        }
#pragma unroll
        for (int p = 0; p < 2; p++) {
            uint32_t off = (uint32_t)((warp_n * 32 + p * 16 + rB) * 128 + kb + bB);
            LDSM4(Bl[p], bufb + BL_OFF + SW(off));
        }
#pragma unroll
        for (int f = 0; f < 4; f++)
#pragma unroll
            for (int nf = 0; nf < 4; nf++)
                MMA(c[f][nf], Af[f], Bh[nf >> 1][(nf & 1) * 2], Bh[nf >> 1][(nf & 1) * 2 + 1]);
#pragma unroll
        for (int f = 0; f < 4; f++)
#pragma unroll
            for (int nf = 0; nf < 4; nf++)
                MMA(c[f][nf], Af[f], Bl[nf >> 1][(nf & 1) * 2], Bl[nf >> 1][(nf & 1) * 2 + 1]);
        // reload A with lo part (reuses Af registers)
#pragma unroll
        for (int f = 0; f < 4; f++) {
            uint32_t off = (uint32_t)((warp_m * 64 + f * 16 + rA) * 128 + kb + bA);
            LDSM4(Af[f], bufb + AL_OFF + SW(off));
        }
#pragma unroll
        for (int f = 0; f < 4; f++)
#pragma unroll
            for (int nf = 0; nf < 4; nf++)
                MMA(c[f][nf], Af[f], Bh[nf >> 1][(nf & 1) * 2], Bh[nf >> 1][(nf & 1) * 2 + 1]);
    }
}

// ---------------------------------------------------------------------------
// Kernel 0: reset cursors + zero output
// ---------------------------------------------------------------------------
__global__ void k_zero(float* __restrict__ out, int n_elems) {
    if (blockIdx.x == 0 && threadIdx.x < E_) g_cursor[threadIdx.x] = 0;
    int i = blockIdx.x * blockDim.x + threadIdx.x;
    int stride = gridDim.x * blockDim.x;
    float4 z = make_float4(0.f, 0.f, 0.f, 0.f);
    for (int idx = i; idx * 4 < n_elems; idx += stride)
        reinterpret_cast<float4*>(out)[idx] = z;
}

// ---------------------------------------------------------------------------
// Kernel 1: gating (one warp per token)
// ---------------------------------------------------------------------------
__global__ void k_gate(const float* __restrict__ x, const float* __restrict__ gw) {
    int warp = threadIdx.x >> 5;
    int lane = threadIdx.x & 31;
    int t = blockIdx.x * 8 + warp;
    const float* xr = x + (size_t)t * D_;

    float xv[32];
#pragma unroll
    for (int i = 0; i < 32; i++) xv[i] = xr[i * 32 + lane];

    float logit[E_];
#pragma unroll
    for (int e = 0; e < E_; e++) {
        const float* wr = gw + e * D_;
        float acc = 0.f;
#pragma unroll
        for (int i = 0; i < 32; i++) acc = fmaf(xv[i], wr[i * 32 + lane], acc);
#pragma unroll
        for (int s = 16; s > 0; s >>= 1) acc += __shfl_xor_sync(0xffffffffu, acc, s);
        logit[e] = acc;
    }

    if (lane == 0) {
        int e0 = 0;
#pragma unroll
        for (int e = 1; e < E_; e++) if (logit[e] > logit[e0]) e0 = e;
        int e1 = (e0 == 0) ? 1 : 0;
#pragma unroll
        for (int e = 0; e < E_; e++) if (e != e0 && logit[e] > logit[e1]) e1 = e;

        float m  = logit[e0];
        float x0 = expf(logit[e0] - m);
        float x1 = expf(logit[e1] - m);
        float inv = 1.f / (x0 + x1);

        int p0 = atomicAdd(&g_cursor[e0], 1);
        g_tok[e0 * T_ + p0] = t;  g_wgt[e0 * T_ + p0] = x0 * inv;
        int p1 = atomicAdd(&g_cursor[e1], 1);
        g_tok[e1 * T_ + p1] = t;  g_wgt[e1 * T_ + p1] = x1 * inv;
    }
}

// ---------------------------------------------------------------------------
// Kernel 2: fused fp32 -> bf16 hi/lo split of x, wfc, wpj (one launch)
// ---------------------------------------------------------------------------
#define N4_X (T_ * D_ / 4)
#define N4_W (E_ * F_ * D_ / 4)

__global__ void k_split3(const float4* __restrict__ x,
                         const float4* __restrict__ wfc,
                         const float4* __restrict__ wpj) {
    const int total = N4_X + 2 * N4_W;
    int i = blockIdx.x * blockDim.x + threadIdx.x;
    int stride = gridDim.x * blockDim.x;
    for (int idx = i; idx < total; idx += stride) {
        const float4* s; uint2 *H, *L; int k;
        if (idx < N4_X) {
            s = x; k = idx;
            H = (uint2*)g_xh; L = (uint2*)g_xl;
        } else if (idx < N4_X + N4_W) {
            s = wfc; k = idx - N4_X;
            H = (uint2*)g_wfh; L = (uint2*)g_wfl;
        } else {
            s = wpj; k = idx - N4_X - N4_W;
            H = (uint2*)g_wph; L = (uint2*)g_wpl;
        }
        float4 v = s[k];
        uint2 Hv, Lv;
        split2(v.x, v.y, Hv.x, Lv.x);
        split2(v.z, v.w, Hv.y, Lv.y);
        H[k] = Hv; L[k] = Lv;
    }
}

// ---------------------------------------------------------------------------
// Kernel 3: GEMM1  H = gelu(gather(X) @ Wfc[e]^T + b)  (bf16 HMMA, 3-term)
// grid (T/128, F/128, E)  -- row-tiles fastest for L2 weight reuse
// ---------------------------------------------------------------------------
__global__ void __launch_bounds__(NTH, 1)
k_fc_mma(const float* __restrict__ bfc) {
    int e = blockIdx.z;
    int cnt = g_cursor[e];
    int row0 = blockIdx.x * BM;
    if (row0 >= cnt) return;
    int n0 = blockIdx.y * BN;
    int hbase = expert_base(e);

    extern __shared__ __align__(1024) char smem[];
    __shared__ int s_toff[BM];
    int tid = threadIdx.x, wid = tid >> 5, lane = tid & 31;
    uint32_t sb = smem_u32(smem);

    if (tid < BM) s_toff[tid] = g_tok[e * T_ + min(row0 + tid, cnt - 1)] * D_;
    __syncthreads();

    int warp_m = wid >> 2, warp_n = wid & 3;   // 2 x 4 warps, tile 64x32
    int g = lane >> 3, l8 = lane & 7;
    int rA = (g & 1) * 8 + l8, bA = (g >> 1) * 16;
    int rB = (g >> 1) * 8 + l8, bB = (g & 1) * 16;

    // copy coords: per-array 1024 16B units; 4 per thread (128B rows)
    int ur[4], uc[4];
#pragma unroll
    for (int j = 0; j < 4; j++) { int u = tid + j * NTH; ur[j] = u >> 3; uc[j] = u & 7; }

    const __nv_bfloat16* wh = g_wfh + (size_t)e * F_ * D_;
    const __nv_bfloat16* wl = g_wfl + (size_t)e * F_ * D_;

#define FC_ISSUE(ci, bsel)                                                      \
    {                                                                           \
        uint32_t bufb = sb + (bsel) * BUF_B;                                    \
        int k0 = (ci) * KC;                                                     \
        _Pragma("unroll")                                                       \
        for (int j = 0; j < 4; j++) {                                           \
            uint32_t dst = SW((uint32_t)(ur[j] * 128 + uc[j] * 16));            \
            size_t ao = (size_t)s_toff[ur[j]] + k0 + uc[j] * 8;                 \
            size_t bo = (size_t)(n0 + ur[j]) * D_ + k0 + uc[j] * 8;             \
            CPA(bufb + AH_OFF + dst, g_xh + ao);                                \
            CPA(bufb + AL_OFF + dst, g_xl + ao);                                \
            CPA(bufb + BH_OFF + dst, wh + bo);                                  \
            CPA(bufb + BL_OFF + dst, wl + bo);                                  \
        }                                                                       \
        CPA_COMMIT();                                                           \
    }

    FC_ISSUE(0, 0);

    float c[4][4][4];
#pragma unroll
    for (int f = 0; f < 4; f++)
#pragma unroll
        for (int nf = 0; nf < 4; nf++)
#pragma unroll
            for (int q = 0; q < 4; q++) c[f][nf][q] = 0.f;

    const int KCH = D_ / KC;   // 16
    for (int i = 0; i < KCH; i++) {
        if (i + 1 < KCH) {
            FC_ISSUE(i + 1, (i + 1) & 1);
            asm volatile("cp.async.wait_group 1;" ::: "memory");
        } else {
            asm volatile("cp.async.wait_group 0;" ::: "memory");
        }
        __syncthreads();
        mma_chunk(sb + (i & 1) * BUF_B, warp_m, warp_n, rA, bA, rB, bB, c);
        __syncthreads();
    }
#undef FC_ISSUE

    // Epilogue: bias + gelu -> split bf16 hi/lo into g_hh/g_hl
    int qr = lane >> 2, qc = (lane & 3) * 2;
#pragma unroll
    for (int f = 0; f < 4; f++) {
#pragma unroll
        for (int pr = 0; pr < 2; pr++) {
            int r = row0 + warp_m * 64 + f * 16 + qr + pr * 8;
            if (r >= cnt) continue;
            size_t hr = (size_t)(hbase + r);
#pragma unroll
            for (int nf = 0; nf < 4; nf++) {
                int n = n0 + warp_n * 32 + nf * 8 + qc;
                float v0 = ngelu(c[f][nf][pr * 2 + 0] + bfc[e * F_ + n]);
                float v1 = ngelu(c[f][nf][pr * 2 + 1] + bfc[e * F_ + n + 1]);
                uint32_t h01, l01;
                split2(v0, v1, h01, l01);
                *reinterpret_cast<uint32_t*>(g_hh + hr * F_ + n) = h01;
                *reinterpret_cast<uint32_t*>(g_hl + hr * F_ + n) = l01;
            }
        }
    }
}

// ---------------------------------------------------------------------------
// Kernel 4: GEMM2  out[token] += w * (H @ Wproj[e]^T + b)
// grid (T/128, D/128, E)  -- row-tiles fastest for L2 weight reuse
// ---------------------------------------------------------------------------
__global__ void __launch_bounds__(NTH, 1)
k_proj_mma(const float* __restrict__ bpj, float* __restrict__ out) {
    int e = blockIdx.z;
    int cnt = g_cursor[e];
    int row0 = blockIdx.x * BM;
    if (row0 >= cnt) return;
    int n0 = blockIdx.y * BN;
    int hbase = expert_base(e);

    extern __shared__ __align__(1024) char smem[];
    __shared__ int   s_hrow[BM];
    __shared__ int   s_tok[BM];
    __shared__ float s_wgt[BM];
    int tid = threadIdx.x, wid = tid >> 5, lane = tid & 31;
    uint32_t sb = smem_u32(smem);

    if (tid < BM) {
        int r = min(row0 + tid, cnt - 1);
        s_hrow[tid] = hbase + r;
        s_tok[tid]  = g_tok[e * T_ + r];
        s_wgt[tid]  = g_wgt[e * T_ + r];
    }
    __syncthreads();

    int warp_m = wid >> 2, warp_n = wid & 3;
    int g = lane >> 3, l8 = lane & 7;
    int rA = (g & 1) * 8 + l8, bA = (g >> 1) * 16;
    int rB = (g >> 1) * 8 + l8, bB = (g & 1) * 16;

    int ur[4], uc[4];
#pragma unroll
    for (int j = 0; j < 4; j++) { int u = tid + j * NTH; ur[j] = u >> 3; uc[j] = u & 7; }

    const __nv_bfloat16* wh = g_wph + (size_t)e * D_ * F_;
    const __nv_bfloat16* wl = g_wpl + (size_t)e * D_ * F_;

#define PJ_ISSUE(ci, bsel)                                                      \
    {                                                                           \
        uint32_t bufb = sb + (bsel) * BUF_B;                                    \
        int k0 = (ci) * KC;                                                     \
        _Pragma("unroll")                                                       \
        for (int j = 0; j < 4; j++) {                                           \
            uint32_t dst = SW((uint32_t)(ur[j] * 128 + uc[j] * 16));            \
            size_t ao = (size_t)s_hrow[ur[j]] * F_ + k0 + uc[j] * 8;            \
            size_t bo = (size_t)(n0 + ur[j]) * F_ + k0 + uc[j] * 8;             \
            CPA(bufb + AH_OFF + dst, g_hh + ao);                                \
            CPA(bufb + AL_OFF + dst, g_hl + ao);                                \
            CPA(bufb + BH_OFF + dst, wh + bo);                                  \
            CPA(bufb + BL_OFF + dst, wl + bo);                                  \
        }                                                                       \
        CPA_COMMIT();                                                           \
    }

    PJ_ISSUE(0, 0);

    float c[4][4][4];
#pragma unroll
    for (int f = 0; f < 4; f++)
#pragma unroll
        for (int nf = 0; nf < 4; nf++)
#pragma unroll
            for (int q = 0; q < 4; q++) c[f][nf][q] = 0.f;

    const int KCH = F_ / KC;   // 64
    for (int i = 0; i < KCH; i++) {
        if (i + 1 < KCH) {
            PJ_ISSUE(i + 1, (i + 1) & 1);
            asm volatile("cp.async.wait_group 1;" ::: "memory");
        } else {
            asm volatile("cp.async.wait_group 0;" ::: "memory");
        }
        __syncthreads();
        mma_chunk(sb + (i & 1) * BUF_B, warp_m, warp_n, rA, bA, rB, bB, c);
        __syncthreads();
    }
#undef PJ_ISSUE

    // Epilogue: (acc + bias) * routing weight, atomic scatter (2 adds/elem total)
    int qr = lane >> 2, qc = (lane & 3) * 2;
#pragma unroll
    for (int f = 0; f < 4; f++) {
#pragma unroll
        for (int pr = 0; pr < 2; pr++) {
            int rl = warp_m * 64 + f * 16 + qr + pr * 8;
            int r = row0 + rl;
            if (r >= cnt) continue;
            int   token = s_tok[rl];
            float w     = s_wgt[rl];
            float* orow = out + (size_t)token * D_;
#pragma unroll
            for (int nf = 0; nf < 4; nf++) {
                int n = n0 + warp_n * 32 + nf * 8 + qc;
                atomicAdd(orow + n,     (c[f][nf][pr * 2 + 0] + bpj[e * D_ + n])     * w);
                atomicAdd(orow + n + 1, (c[f][nf][pr * 2 + 1] + bpj[e * D_ + n + 1]) * w);
            }
        }
    }
}

// ---------------------------------------------------------------------------
// Launch: 5 launches; k_fc_mma at index 3 (confirmed ncu capture slot).
// ---------------------------------------------------------------------------
extern "C" void kernel_launch(void* const* d_in, const int* in_sizes, int n_in,
                              void* d_out, int out_size) {
    const float* x   = (const float*)d_in[0];
    const float* gw  = (const float*)d_in[1];
    const float* wfc = (const float*)d_in[2];
    const float* bfc = (const float*)d_in[3];
    const float* wpj = (const float*)d_in[4];
    const float* bpj = (const float*)d_in[5];
    float* out = (float*)d_out;

    cudaFuncSetAttribute(k_fc_mma,   cudaFuncAttributeMaxDynamicSharedMemorySize, SMEM_DYN);
    cudaFuncSetAttribute(k_proj_mma, cudaFuncAttributeMaxDynamicSharedMemorySize, SMEM_DYN);

    k_zero  <<<2048, 256>>>(out, out_size);                                    // 0
    k_gate  <<<T_ / 8, 256>>>(x, gw);                                          // 1
    k_split3<<<8192, 256>>>((const float4*)x, (const float4*)wfc,
                            (const float4*)wpj);                               // 2
    k_fc_mma  <<<dim3(T_ / BM, F_ / BN, E_), NTH, SMEM_DYN>>>(bfc);            // 3 <- ncu
    k_proj_mma<<<dim3(T_ / BM, D_ / BN, E_), NTH, SMEM_DYN>>>(bpj, out);       // 4
}

// round 11
// speedup vs baseline: 1.2006x; 1.0194x over previous
#include <cuda_runtime.h>
#include <cuda_bf16.h>
#include <math.h>
#include <stdint.h>

// Problem constants
#define E_  8
#define D_  1024
#define F_  4096
#define T_  8192
#define TK_ (T_ * 2)

// GEMM tiling: 128x128 block, 256 threads, warp tile 64x32,
// KC=64 chunk (128B bf16 rows, SW128 swizzle), 3-stage cp.async pipeline
// (192 KB smem, ONE __syncthreads per chunk).
#define BM 128
#define BN 128
#define KC 64
#define NTH 256
#define AH_OFF 0
#define AL_OFF 16384
#define BH_OFF 32768
#define BL_OFF 49152
#define STAGE_B 65536
#define NSTAGE 3
#define SMEM_DYN (NSTAGE * STAGE_B)   // 192 KB

// ---------------------------------------------------------------------------
// Device scratch (static: no allocations allowed)
// ---------------------------------------------------------------------------
__device__ __nv_bfloat16 g_xh[(size_t)T_ * D_];
__device__ __nv_bfloat16 g_xl[(size_t)T_ * D_];
__device__ __nv_bfloat16 g_wfh[(size_t)E_ * F_ * D_];
__device__ __nv_bfloat16 g_wfl[(size_t)E_ * F_ * D_];
__device__ __nv_bfloat16 g_wph[(size_t)E_ * D_ * F_];
__device__ __nv_bfloat16 g_wpl[(size_t)E_ * D_ * F_];
__device__ __nv_bfloat16 g_hh[(size_t)TK_ * F_];
__device__ __nv_bfloat16 g_hl[(size_t)TK_ * F_];
__device__ int   g_tok[E_ * T_];
__device__ float g_wgt[E_ * T_];
__device__ int   g_cursor[E_];

// ---------------------------------------------------------------------------
// Helpers
// ---------------------------------------------------------------------------
static __device__ __forceinline__ uint32_t smem_u32(const void* p) {
    uint32_t a;
    asm("{ .reg .u64 t; cvta.to.shared.u64 t, %1; cvt.u32.u64 %0, t; }"
        : "=r"(a) : "l"(p));
    return a;
}

#define SW(o) ((o) ^ (((o) >> 3) & 0x70))

#define CPA(dst, src) \
    asm volatile("cp.async.cg.shared.global [%0], [%1], 16;" \
                 :: "r"(dst), "l"(src) : "memory")
#define CPA_COMMIT() asm volatile("cp.async.commit_group;" ::: "memory")

#define LDSM4(r, addr) \
    asm volatile("ldmatrix.sync.aligned.m8n8.x4.shared.b16 {%0,%1,%2,%3}, [%4];" \
                 : "=r"((r)[0]), "=r"((r)[1]), "=r"((r)[2]), "=r"((r)[3]) \
                 : "r"(addr))

#define MMA(cd, a, b0, b1) \
    asm volatile("mma.sync.aligned.m16n8k16.row.col.f32.bf16.bf16.f32 " \
                 "{%0,%1,%2,%3}, {%4,%5,%6,%7}, {%8,%9}, {%0,%1,%2,%3};" \
                 : "+f"((cd)[0]), "+f"((cd)[1]), "+f"((cd)[2]), "+f"((cd)[3]) \
                 : "r"((a)[0]), "r"((a)[1]), "r"((a)[2]), "r"((a)[3]), \
                   "r"(b0), "r"(b1))

static __device__ __forceinline__ float ngelu(float v) {
    float u = 0.7978845608028654f * (v + 0.044715f * v * v * v);
    return 0.5f * v * (1.0f + tanhf(u));
}

// Local prefix of expert bucket bases (gate finished before GEMM launches)
static __device__ __forceinline__ int expert_base(int e) {
    int b = 0;
#pragma unroll
    for (int j = 0; j < E_; j++) if (j < e) b += g_cursor[j];
    return b;
}

// Packed split of two fp32 into bf16-hi pair + bf16-lo pair
static __device__ __forceinline__ void split2(float v0, float v1,
                                              uint32_t& h01, uint32_t& l01) {
    asm("cvt.rn.bf16x2.f32 %0, %1, %2;" : "=r"(h01) : "f"(v1), "f"(v0));
    float r0 = __uint_as_float(h01 << 16);
    float r1 = __uint_as_float(h01 & 0xFFFF0000u);
    asm("cvt.rn.bf16x2.f32 %0, %1, %2;" : "=r"(l01) : "f"(v1 - r1), "f"(v0 - r0));
}

// One K=64 chunk of the 3-term split MMA (Ah*Bh + Ah*Bl + Al*Bh).
// Warp tile 64(M) x 32(N): 4 M-frags, 4 N-frags, 64 accumulators.
static __device__ __forceinline__ void mma_chunk(
    uint32_t bufb, int warp_m, int warp_n,
    int rA, int bA, int rB, int bB, float (&c)[4][4][4]) {
#pragma unroll
    for (int ks = 0; ks < 4; ks++) {
        int kb = ks * 32;
        uint32_t Af[4][4], Bh[2][4], Bl[2][4];
#pragma unroll
        for (int f = 0; f < 4; f++) {
            uint32_t off = (uint32_t)((warp_m * 64 + f * 16 + rA) * 128 + kb + bA);
            LDSM4(Af[f], bufb + AH_OFF + SW(off));
        }
#pragma unroll
        for (int p = 0; p < 2; p++) {
            uint32_t off = (uint32_t)((warp_n * 32 + p * 16 + rB) * 128 + kb + bB);
            LDSM4(Bh[p], bufb + BH_OFF + SW(off));
        }
#pragma unroll
        for (int p = 0; p < 2; p++) {
            uint32_t off = (uint32_t)((warp_n * 32 + p * 16 + rB) * 128 + kb + bB);
            LDSM4(Bl[p], bufb + BL_OFF + SW(off));
        }
#pragma unroll
        for (int f = 0; f < 4; f++)
#pragma unroll
            for (int nf = 0; nf < 4; nf++)
                MMA(c[f][nf], Af[f], Bh[nf >> 1][(nf & 1) * 2], Bh[nf >> 1][(nf & 1) * 2 + 1]);
#pragma unroll
        for (int f = 0; f < 4; f++)
#pragma unroll
            for (int nf = 0; nf < 4; nf++)
                MMA(c[f][nf], Af[f], Bl[nf >> 1][(nf & 1) * 2], Bl[nf >> 1][(nf & 1) * 2 + 1]);
        // reload A with lo part (reuses Af registers)
#pragma unroll
        for (int f = 0; f < 4; f++) {
            uint32_t off = (uint32_t)((warp_m * 64 + f * 16 + rA) * 128 + kb + bA);
            LDSM4(Af[f], bufb + AL_OFF + SW(off));
        }
#pragma unroll
        for (int f = 0; f < 4; f++)
#pragma unroll
            for (int nf = 0; nf < 4; nf++)
                MMA(c[f][nf], Af[f], Bh[nf >> 1][(nf & 1) * 2], Bh[nf >> 1][(nf & 1) * 2 + 1]);
    }
}

// ---------------------------------------------------------------------------
// Kernel 0: reset cursors + zero output
// ---------------------------------------------------------------------------
__global__ void k_zero(float* __restrict__ out, int n_elems) {
    if (blockIdx.x == 0 && threadIdx.x < E_) g_cursor[threadIdx.x] = 0;
    int i = blockIdx.x * blockDim.x + threadIdx.x;
    int stride = gridDim.x * blockDim.x;
    float4 z = make_float4(0.f, 0.f, 0.f, 0.f);
    for (int idx = i; idx * 4 < n_elems; idx += stride)
        reinterpret_cast<float4*>(out)[idx] = z;
}

// ---------------------------------------------------------------------------
// Kernel 1: gating (one warp per token)
// ---------------------------------------------------------------------------
__global__ void k_gate(const float* __restrict__ x, const float* __restrict__ gw) {
    int warp = threadIdx.x >> 5;
    int lane = threadIdx.x & 31;
    int t = blockIdx.x * 8 + warp;
    const float* xr = x + (size_t)t * D_;

    float xv[32];
#pragma unroll
    for (int i = 0; i < 32; i++) xv[i] = xr[i * 32 + lane];

    float logit[E_];
#pragma unroll
    for (int e = 0; e < E_; e++) {
        const float* wr = gw + e * D_;
        float acc = 0.f;
#pragma unroll
        for (int i = 0; i < 32; i++) acc = fmaf(xv[i], wr[i * 32 + lane], acc);
#pragma unroll
        for (int s = 16; s > 0; s >>= 1) acc += __shfl_xor_sync(0xffffffffu, acc, s);
        logit[e] = acc;
    }

    if (lane == 0) {
        int e0 = 0;
#pragma unroll
        for (int e = 1; e < E_; e++) if (logit[e] > logit[e0]) e0 = e;
        int e1 = (e0 == 0) ? 1 : 0;
#pragma unroll
        for (int e = 0; e < E_; e++) if (e != e0 && logit[e] > logit[e1]) e1 = e;

        float m  = logit[e0];
        float x0 = expf(logit[e0] - m);
        float x1 = expf(logit[e1] - m);
        float inv = 1.f / (x0 + x1);

        int p0 = atomicAdd(&g_cursor[e0], 1);
        g_tok[e0 * T_ + p0] = t;  g_wgt[e0 * T_ + p0] = x0 * inv;
        int p1 = atomicAdd(&g_cursor[e1], 1);
        g_tok[e1 * T_ + p1] = t;  g_wgt[e1 * T_ + p1] = x1 * inv;
    }
}

// ---------------------------------------------------------------------------
// Kernel 2: fused fp32 -> bf16 hi/lo split of x, wfc, wpj (one launch)
// ---------------------------------------------------------------------------
#define N4_X (T_ * D_ / 4)
#define N4_W (E_ * F_ * D_ / 4)

__global__ void k_split3(const float4* __restrict__ x,
                         const float4* __restrict__ wfc,
                         const float4* __restrict__ wpj) {
    const int total = N4_X + 2 * N4_W;
    int i = blockIdx.x * blockDim.x + threadIdx.x;
    int stride = gridDim.x * blockDim.x;
    for (int idx = i; idx < total; idx += stride) {
        const float4* s; uint2 *H, *L; int k;
        if (idx < N4_X) {
            s = x; k = idx;
            H = (uint2*)g_xh; L = (uint2*)g_xl;
        } else if (idx < N4_X + N4_W) {
            s = wfc; k = idx - N4_X;
            H = (uint2*)g_wfh; L = (uint2*)g_wfl;
        } else {
            s = wpj; k = idx - N4_X - N4_W;
            H = (uint2*)g_wph; L = (uint2*)g_wpl;
        }
        float4 v = s[k];
        uint2 Hv, Lv;
        split2(v.x, v.y, Hv.x, Lv.x);
        split2(v.z, v.w, Hv.y, Lv.y);
        H[k] = Hv; L[k] = Lv;
    }
}

// ---------------------------------------------------------------------------
// Kernel 3: GEMM1  H = gelu(gather(X) @ Wfc[e]^T + b)  (bf16 HMMA, 3-term)
// grid (T/128, F/128, E)  -- row-tiles fastest for L2 weight reuse
// ---------------------------------------------------------------------------
__global__ void __launch_bounds__(NTH, 1)
k_fc_mma(const float* __restrict__ bfc) {
    int e = blockIdx.z;
    int cnt = g_cursor[e];
    int row0 = blockIdx.x * BM;
    if (row0 >= cnt) return;
    int n0 = blockIdx.y * BN;
    int hbase = expert_base(e);

    extern __shared__ __align__(1024) char smem[];
    __shared__ int s_toff[BM];
    int tid = threadIdx.x, wid = tid >> 5, lane = tid & 31;
    uint32_t sb = smem_u32(smem);

    if (tid < BM) s_toff[tid] = g_tok[e * T_ + min(row0 + tid, cnt - 1)] * D_;
    __syncthreads();

    int warp_m = wid >> 2, warp_n = wid & 3;   // 2 x 4 warps, tile 64x32
    int g = lane >> 3, l8 = lane & 7;
    int rA = (g & 1) * 8 + l8, bA = (g >> 1) * 16;
    int rB = (g >> 1) * 8 + l8, bB = (g & 1) * 16;

    // copy coords: per-array 1024 16B units; 4 per thread (128B rows)
    int ur[4], uc[4];
#pragma unroll
    for (int j = 0; j < 4; j++) { int u = tid + j * NTH; ur[j] = u >> 3; uc[j] = u & 7; }

    const __nv_bfloat16* wh = g_wfh + (size_t)e * F_ * D_;
    const __nv_bfloat16* wl = g_wfl + (size_t)e * F_ * D_;

#define FC_ISSUE(ci, sg)                                                        \
    {                                                                           \
        uint32_t bufb = sb + (sg) * STAGE_B;                                    \
        int k0 = (ci) * KC;                                                     \
        _Pragma("unroll")                                                       \
        for (int j = 0; j < 4; j++) {                                           \
            uint32_t dst = SW((uint32_t)(ur[j] * 128 + uc[j] * 16));            \
            size_t ao = (size_t)s_toff[ur[j]] + k0 + uc[j] * 8;                 \
            size_t bo = (size_t)(n0 + ur[j]) * D_ + k0 + uc[j] * 8;             \
            CPA(bufb + AH_OFF + dst, g_xh + ao);                                \
            CPA(bufb + AL_OFF + dst, g_xl + ao);                                \
            CPA(bufb + BH_OFF + dst, wh + bo);                                  \
            CPA(bufb + BL_OFF + dst, wl + bo);                                  \
        }                                                                       \
        CPA_COMMIT();                                                           \
    }

    FC_ISSUE(0, 0);
    FC_ISSUE(1, 1);

    float c[4][4][4];
#pragma unroll
    for (int f = 0; f < 4; f++)
#pragma unroll
        for (int nf = 0; nf < 4; nf++)
#pragma unroll
            for (int q = 0; q < 4; q++) c[f][nf][q] = 0.f;

    const int KCH = D_ / KC;   // 16
    int stage = 0;
    for (int i = 0; i < KCH; i++) {
        if (i < KCH - 1) asm volatile("cp.async.wait_group 1;" ::: "memory");
        else             asm volatile("cp.async.wait_group 0;" ::: "memory");
        __syncthreads();
        if (i + 2 < KCH) {
            int sg = stage + 2; if (sg >= NSTAGE) sg -= NSTAGE;
            FC_ISSUE(i + 2, sg);
        }
        mma_chunk(sb + stage * STAGE_B, warp_m, warp_n, rA, bA, rB, bB, c);
        if (++stage == NSTAGE) stage = 0;
    }
#undef FC_ISSUE

    // Epilogue: bias + gelu -> split bf16 hi/lo into g_hh/g_hl
    int qr = lane >> 2, qc = (lane & 3) * 2;
#pragma unroll
    for (int f = 0; f < 4; f++) {
#pragma unroll
        for (int pr = 0; pr < 2; pr++) {
            int r = row0 + warp_m * 64 + f * 16 + qr + pr * 8;
            if (r >= cnt) continue;
            size_t hr = (size_t)(hbase + r);
#pragma unroll
            for (int nf = 0; nf < 4; nf++) {
                int n = n0 + warp_n * 32 + nf * 8 + qc;
                float v0 = ngelu(c[f][nf][pr * 2 + 0] + bfc[e * F_ + n]);
                float v1 = ngelu(c[f][nf][pr * 2 + 1] + bfc[e * F_ + n + 1]);
                uint32_t h01, l01;
                split2(v0, v1, h01, l01);
                *reinterpret_cast<uint32_t*>(g_hh + hr * F_ + n) = h01;
                *reinterpret_cast<uint32_t*>(g_hl + hr * F_ + n) = l01;
            }
        }
    }
}

// ---------------------------------------------------------------------------
// Kernel 4: GEMM2  out[token] += w * (H @ Wproj[e]^T + b)
// grid (T/128, D/128, E)  -- row-tiles fastest for L2 weight reuse
// ---------------------------------------------------------------------------
__global__ void __launch_bounds__(NTH, 1)
k_proj_mma(const float* __restrict__ bpj, float* __restrict__ out) {
    int e = blockIdx.z;
    int cnt = g_cursor[e];
    int row0 = blockIdx.x * BM;
    if (row0 >= cnt) return;
    int n0 = blockIdx.y * BN;
    int hbase = expert_base(e);

    extern __shared__ __align__(1024) char smem[];
    __shared__ int   s_hrow[BM];
    __shared__ int   s_tok[BM];
    __shared__ float s_wgt[BM];
    int tid = threadIdx.x, wid = tid >> 5, lane = tid & 31;
    uint32_t sb = smem_u32(smem);

    if (tid < BM) {
        int r = min(row0 + tid, cnt - 1);
        s_hrow[tid] = hbase + r;
        s_tok[tid]  = g_tok[e * T_ + r];
        s_wgt[tid]  = g_wgt[e * T_ + r];
    }
    __syncthreads();

    int warp_m = wid >> 2, warp_n = wid & 3;
    int g = lane >> 3, l8 = lane & 7;
    int rA = (g & 1) * 8 + l8, bA = (g >> 1) * 16;
    int rB = (g >> 1) * 8 + l8, bB = (g & 1) * 16;

    int ur[4], uc[4];
#pragma unroll
    for (int j = 0; j < 4; j++) { int u = tid + j * NTH; ur[j] = u >> 3; uc[j] = u & 7; }

    const __nv_bfloat16* wh = g_wph + (size_t)e * D_ * F_;
    const __nv_bfloat16* wl = g_wpl + (size_t)e * D_ * F_;

#define PJ_ISSUE(ci, sg)                                                        \
    {                                                                           \
        uint32_t bufb = sb + (sg) * STAGE_B;                                    \
        int k0 = (ci) * KC;                                                     \
        _Pragma("unroll")                                                       \
        for (int j = 0; j < 4; j++) {                                           \
            uint32_t dst = SW((uint32_t)(ur[j] * 128 + uc[j] * 16));            \
            size_t ao = (size_t)s_hrow[ur[j]] * F_ + k0 + uc[j] * 8;            \
            size_t bo = (size_t)(n0 + ur[j]) * F_ + k0 + uc[j] * 8;             \
            CPA(bufb + AH_OFF + dst, g_hh + ao);                                \
            CPA(bufb + AL_OFF + dst, g_hl + ao);                                \
            CPA(bufb + BH_OFF + dst, wh + bo);                                  \
            CPA(bufb + BL_OFF + dst, wl + bo);                                  \
        }                                                                       \
        CPA_COMMIT();                                                           \
    }

    PJ_ISSUE(0, 0);
    PJ_ISSUE(1, 1);

    float c[4][4][4];
#pragma unroll
    for (int f = 0; f < 4; f++)
#pragma unroll
        for (int nf = 0; nf < 4; nf++)
#pragma unroll
            for (int q = 0; q < 4; q++) c[f][nf][q] = 0.f;

    const int KCH = F_ / KC;   // 64
    int stage = 0;
    for (int i = 0; i < KCH; i++) {
        if (i < KCH - 1) asm volatile("cp.async.wait_group 1;" ::: "memory");
        else             asm volatile("cp.async.wait_group 0;" ::: "memory");
        __syncthreads();
        if (i + 2 < KCH) {
            int sg = stage + 2; if (sg >= NSTAGE) sg -= NSTAGE;
            PJ_ISSUE(i + 2, sg);
        }
        mma_chunk(sb + stage * STAGE_B, warp_m, warp_n, rA, bA, rB, bB, c);
        if (++stage == NSTAGE) stage = 0;
    }
#undef PJ_ISSUE

    // Epilogue: (acc + bias) * routing weight, atomic scatter (2 adds/elem total)
    int qr = lane >> 2, qc = (lane & 3) * 2;
#pragma unroll
    for (int f = 0; f < 4; f++) {
#pragma unroll
        for (int pr = 0; pr < 2; pr++) {
            int rl = warp_m * 64 + f * 16 + qr + pr * 8;
            int r = row0 + rl;
            if (r >= cnt) continue;
            int   token = s_tok[rl];
            float w     = s_wgt[rl];
            float* orow = out + (size_t)token * D_;
#pragma unroll
            for (int nf = 0; nf < 4; nf++) {
                int n = n0 + warp_n * 32 + nf * 8 + qc;
                atomicAdd(orow + n,     (c[f][nf][pr * 2 + 0] + bpj[e * D_ + n])     * w);
                atomicAdd(orow + n + 1, (c[f][nf][pr * 2 + 1] + bpj[e * D_ + n + 1]) * w);
            }
        }
    }
}

// ---------------------------------------------------------------------------
// Launch: 5 launches; k_fc_mma at index 3 (confirmed ncu capture slot).
// ---------------------------------------------------------------------------
extern "C" void kernel_launch(void* const* d_in, const int* in_sizes, int n_in,
                              void* d_out, int out_size) {
    const float* x   = (const float*)d_in[0];
    const float* gw  = (const float*)d_in[1];
    const float* wfc = (const float*)d_in[2];
    const float* bfc = (const float*)d_in[3];
    const float* wpj = (const float*)d_in[4];
    const float* bpj = (const float*)d_in[5];
    float* out = (float*)d_out;

    cudaFuncSetAttribute(k_fc_mma,   cudaFuncAttributeMaxDynamicSharedMemorySize, SMEM_DYN);
    cudaFuncSetAttribute(k_proj_mma, cudaFuncAttributeMaxDynamicSharedMemorySize, SMEM_DYN);

    k_zero  <<<2048, 256>>>(out, out_size);                                    // 0
    k_gate  <<<T_ / 8, 256>>>(x, gw);                                          // 1
    k_split3<<<8192, 256>>>((const float4*)x, (const float4*)wfc,
                            (const float4*)wpj);                               // 2
    k_fc_mma  <<<dim3(T_ / BM, F_ / BN, E_), NTH, SMEM_DYN>>>(bfc);            // 3 <- ncu
    k_proj_mma<<<dim3(T_ / BM, D_ / BN, E_), NTH, SMEM_DYN>>>(bpj, out);       // 4
}

// round 12
// speedup vs baseline: 1.7357x; 1.4456x over previous
#include <cuda_runtime.h>
#include <cuda_bf16.h>
#include <math.h>
#include <stdint.h>

// Problem constants
#define E_  8
#define D_  1024
#define F_  4096
#define T_  8192
#define TK_ (T_ * 2)

// GEMM tiling: 128x128 block, 256 threads, warp tile 64x32,
// KC=64 int8 chunk (64B rows, SW64 swizzle), 3-stage cp.async pipeline.
#define BM 128
#define BN 128
#define KC 64
#define NTH 256
#define AH_OFF 0
#define AL_OFF 8192
#define BH_OFF 16384
#define BL_OFF 24576
#define STAGE_B 32768
#define NSTAGE 3
#define SMEM_DYN (NSTAGE * STAGE_B)   // 96 KB

#define INV127 0.007874015748031496f

// ---------------------------------------------------------------------------
// Device scratch (static: no allocations allowed)
// ---------------------------------------------------------------------------
__device__ int8_t g_xq_h[(size_t)T_ * D_];
__device__ int8_t g_xq_l[(size_t)T_ * D_];
__device__ int8_t g_wfq_h[(size_t)E_ * F_ * D_];
__device__ int8_t g_wfq_l[(size_t)E_ * F_ * D_];
__device__ int8_t g_wpq_h[(size_t)E_ * D_ * F_];
__device__ int8_t g_wpq_l[(size_t)E_ * D_ * F_];
__device__ int8_t g_hq_h[(size_t)TK_ * F_];
__device__ int8_t g_hq_l[(size_t)TK_ * F_];
__device__ float  g_h[(size_t)TK_ * F_];      // fp32 h before quantization
__device__ float  g_sx[T_];
__device__ float  g_swf[E_ * F_];
__device__ float  g_swp[E_ * D_];
__device__ float  g_sh[TK_];
__device__ int    g_tok[E_ * T_];
__device__ float  g_wgt[E_ * T_];
__device__ int    g_cursor[E_];

// ---------------------------------------------------------------------------
// Helpers
// ---------------------------------------------------------------------------
static __device__ __forceinline__ uint32_t smem_u32(const void* p) {
    uint32_t a;
    asm("{ .reg .u64 t; cvta.to.shared.u64 t, %1; cvt.u32.u64 %0, t; }"
        : "=r"(a) : "l"(p));
    return a;
}

// 64B-row swizzle (validated R7/R8): XOR 16B-unit bits with row bits 1-2
#define SW64(o) ((o) ^ (((o) >> 3) & 0x30))

#define CPA(dst, src) \
    asm volatile("cp.async.cg.shared.global [%0], [%1], 16;" \
                 :: "r"(dst), "l"(src) : "memory")
#define CPA_COMMIT() asm volatile("cp.async.commit_group;" ::: "memory")

#define LDSM4(r, addr) \
    asm volatile("ldmatrix.sync.aligned.m8n8.x4.shared.b16 {%0,%1,%2,%3}, [%4];" \
                 : "=r"((r)[0]), "=r"((r)[1]), "=r"((r)[2]), "=r"((r)[3]) \
                 : "r"(addr))

#define IMMA(cd, a, b0, b1) \
    asm volatile("mma.sync.aligned.m16n8k32.row.col.s32.s8.s8.s32 " \
                 "{%0,%1,%2,%3}, {%4,%5,%6,%7}, {%8,%9}, {%0,%1,%2,%3};" \
                 : "+r"((cd)[0]), "+r"((cd)[1]), "+r"((cd)[2]), "+r"((cd)[3]) \
                 : "r"((a)[0]), "r"((a)[1]), "r"((a)[2]), "r"((a)[3]), \
                   "r"(b0), "r"(b1))

static __device__ __forceinline__ float ngelu(float v) {
    float u = 0.7978845608028654f * (v + 0.044715f * v * v * v);
    return 0.5f * v * (1.0f + tanhf(u));
}

static __device__ __forceinline__ int expert_base(int e) {
    int b = 0;
#pragma unroll
    for (int j = 0; j < E_; j++) if (j < e) b += g_cursor[j];
    return b;
}

// Quantize one fp32 to (hi, lo) int8 given inv_s = 127/rowmax, s = rowmax/127
static __device__ __forceinline__ void q2(float v, float inv_s, float s,
                                          signed char& qh, signed char& ql) {
    int a = __float2int_rn(v * inv_s);
    float r = v - s * (float)a;
    int b = __float2int_rn(r * inv_s * 127.0f);
    qh = (signed char)a;
    ql = (signed char)b;
}

// One K=64 int8 chunk of the 3-term split: C0 += Ah*Bh; C1 += Ah*Bl + Al*Bh.
static __device__ __forceinline__ void mma_chunk_i8(
    uint32_t bufb, int warp_m, int warp_n,
    int rA, int bA, int rB, int bB, int (&c0)[4][4][4], int (&c1)[4][4][4]) {
#pragma unroll
    for (int ks = 0; ks < 2; ks++) {
        int kb = ks * 32;
        uint32_t Af[4][4], Bh[2][4], Bl[2][4];
#pragma unroll
        for (int f = 0; f < 4; f++) {
            uint32_t off = (uint32_t)((warp_m * 64 + f * 16 + rA) * 64 + kb + bA);
            LDSM4(Af[f], bufb + AH_OFF + SW64(off));
        }
#pragma unroll
        for (int p = 0; p < 2; p++) {
            uint32_t off = (uint32_t)((warp_n * 32 + p * 16 + rB) * 64 + kb + bB);
            LDSM4(Bh[p], bufb + BH_OFF + SW64(off));
        }
#pragma unroll
        for (int p = 0; p < 2; p++) {
            uint32_t off = (uint32_t)((warp_n * 32 + p * 16 + rB) * 64 + kb + bB);
            LDSM4(Bl[p], bufb + BL_OFF + SW64(off));
        }
#pragma unroll
        for (int f = 0; f < 4; f++)
#pragma unroll
            for (int nf = 0; nf < 4; nf++)
                IMMA(c0[f][nf], Af[f], Bh[nf >> 1][(nf & 1) * 2], Bh[nf >> 1][(nf & 1) * 2 + 1]);
#pragma unroll
        for (int f = 0; f < 4; f++)
#pragma unroll
            for (int nf = 0; nf < 4; nf++)
                IMMA(c1[f][nf], Af[f], Bl[nf >> 1][(nf & 1) * 2], Bl[nf >> 1][(nf & 1) * 2 + 1]);
        // reload A with lo part (reuses Af regs); cross term shares C1 (same 1/127)
#pragma unroll
        for (int f = 0; f < 4; f++) {
            uint32_t off = (uint32_t)((warp_m * 64 + f * 16 + rA) * 64 + kb + bA);
            LDSM4(Af[f], bufb + AL_OFF + SW64(off));
        }
#pragma unroll
        for (int f = 0; f < 4; f++)
#pragma unroll
            for (int nf = 0; nf < 4; nf++)
                IMMA(c1[f][nf], Af[f], Bh[nf >> 1][(nf & 1) * 2], Bh[nf >> 1][(nf & 1) * 2 + 1]);
    }
}

// ---------------------------------------------------------------------------
// Kernel 0: reset cursors + zero output
// ---------------------------------------------------------------------------
__global__ void k_zero(float* __restrict__ out, int n_elems) {
    if (blockIdx.x == 0 && threadIdx.x < E_) g_cursor[threadIdx.x] = 0;
    int i = blockIdx.x * blockDim.x + threadIdx.x;
    int stride = gridDim.x * blockDim.x;
    float4 z = make_float4(0.f, 0.f, 0.f, 0.f);
    for (int idx = i; idx * 4 < n_elems; idx += stride)
        reinterpret_cast<float4*>(out)[idx] = z;
}

// ---------------------------------------------------------------------------
// Kernel 1: gating (one warp per token)
// ---------------------------------------------------------------------------
__global__ void k_gate(const float* __restrict__ x, const float* __restrict__ gw) {
    int warp = threadIdx.x >> 5;
    int lane = threadIdx.x & 31;
    int t = blockIdx.x * 8 + warp;
    const float* xr = x + (size_t)t * D_;

    float xv[32];
#pragma unroll
    for (int i = 0; i < 32; i++) xv[i] = xr[i * 32 + lane];

    float logit[E_];
#pragma unroll
    for (int e = 0; e < E_; e++) {
        const float* wr = gw + e * D_;
        float acc = 0.f;
#pragma unroll
        for (int i = 0; i < 32; i++) acc = fmaf(xv[i], wr[i * 32 + lane], acc);
#pragma unroll
        for (int s = 16; s > 0; s >>= 1) acc += __shfl_xor_sync(0xffffffffu, acc, s);
        logit[e] = acc;
    }

    if (lane == 0) {
        int e0 = 0;
#pragma unroll
        for (int e = 1; e < E_; e++) if (logit[e] > logit[e0]) e0 = e;
        int e1 = (e0 == 0) ? 1 : 0;
#pragma unroll
        for (int e = 0; e < E_; e++) if (e != e0 && logit[e] > logit[e1]) e1 = e;

        float m  = logit[e0];
        float x0 = expf(logit[e0] - m);
        float x1 = expf(logit[e1] - m);
        float inv = 1.f / (x0 + x1);

        int p0 = atomicAdd(&g_cursor[e0], 1);
        g_tok[e0 * T_ + p0] = t;  g_wgt[e0 * T_ + p0] = x0 * inv;
        int p1 = atomicAdd(&g_cursor[e1], 1);
        g_tok[e1 * T_ + p1] = t;  g_wgt[e1 * T_ + p1] = x1 * inv;
    }
}

// ---------------------------------------------------------------------------
// Kernel 2: row-wise 2-level int8 quantization of x, wfc, wpj (one launch).
// One block per row; row max -> scale -> hi/lo int8.
// ---------------------------------------------------------------------------
__global__ void k_quantA(const float* __restrict__ x,
                         const float* __restrict__ wfc,
                         const float* __restrict__ wpj) {
    __shared__ float s_max[8];
    __shared__ float s_scale[2];
    int b = blockIdx.x, tid = threadIdx.x;

    const float* row; int8_t *qh, *ql; float* sc; int nvec;  // nvec float4 per thread
    if (b < T_) {
        row = x + (size_t)b * D_;
        qh = g_xq_h + (size_t)b * D_;  ql = g_xq_l + (size_t)b * D_;
        sc = &g_sx[b]; nvec = 1;
    } else if (b < T_ + E_ * F_) {
        int r = b - T_;
        row = wfc + (size_t)r * D_;
        qh = g_wfq_h + (size_t)r * D_; ql = g_wfq_l + (size_t)r * D_;
        sc = &g_swf[r]; nvec = 1;
    } else {
        int r = b - T_ - E_ * F_;
        row = wpj + (size_t)r * F_;
        qh = g_wpq_h + (size_t)r * F_; ql = g_wpq_l + (size_t)r * F_;
        sc = &g_swp[r]; nvec = 4;
    }

    float4 v[4];
    float m = 0.f;
    for (int i = 0; i < nvec; i++) {
        v[i] = reinterpret_cast<const float4*>(row)[tid + i * NTH];
        m = fmaxf(m, fmaxf(fmaxf(fabsf(v[i].x), fabsf(v[i].y)),
                           fmaxf(fabsf(v[i].z), fabsf(v[i].w))));
    }
#pragma unroll
    for (int s = 16; s > 0; s >>= 1) m = fmaxf(m, __shfl_xor_sync(0xffffffffu, m, s));
    if ((tid & 31) == 0) s_max[tid >> 5] = m;
    __syncthreads();
    if (tid == 0) {
        float mm = s_max[0];
#pragma unroll
        for (int w = 1; w < 8; w++) mm = fmaxf(mm, s_max[w]);
        mm = fmaxf(mm, 1e-30f);
        s_scale[0] = mm / 127.0f;        // s
        s_scale[1] = 127.0f / mm;        // 1/s
        *sc = mm / 127.0f;
    }
    __syncthreads();
    float s = s_scale[0], inv_s = s_scale[1];

    for (int i = 0; i < nvec; i++) {
        signed char h0, l0, h1, l1, h2, l2, h3, l3;
        q2(v[i].x, inv_s, s, h0, l0);
        q2(v[i].y, inv_s, s, h1, l1);
        q2(v[i].z, inv_s, s, h2, l2);
        q2(v[i].w, inv_s, s, h3, l3);
        reinterpret_cast<char4*>(qh)[tid + i * NTH] = make_char4(h0, h1, h2, h3);
        reinterpret_cast<char4*>(ql)[tid + i * NTH] = make_char4(l0, l1, l2, l3);
    }
}

// ---------------------------------------------------------------------------
// Kernel 4: row-wise quantization of h (bucket-ordered, rows of F)
// ---------------------------------------------------------------------------
__global__ void k_quantH() {
    __shared__ float s_max[8];
    __shared__ float s_scale[2];
    int b = blockIdx.x, tid = threadIdx.x;
    const float* row = g_h + (size_t)b * F_;
    int8_t* qh = g_hq_h + (size_t)b * F_;
    int8_t* ql = g_hq_l + (size_t)b * F_;

    float4 v[4];
    float m = 0.f;
#pragma unroll
    for (int i = 0; i < 4; i++) {
        v[i] = reinterpret_cast<const float4*>(row)[tid + i * NTH];
        m = fmaxf(m, fmaxf(fmaxf(fabsf(v[i].x), fabsf(v[i].y)),
                           fmaxf(fabsf(v[i].z), fabsf(v[i].w))));
    }
#pragma unroll
    for (int s = 16; s > 0; s >>= 1) m = fmaxf(m, __shfl_xor_sync(0xffffffffu, m, s));
    if ((tid & 31) == 0) s_max[tid >> 5] = m;
    __syncthreads();
    if (tid == 0) {
        float mm = s_max[0];
#pragma unroll
        for (int w = 1; w < 8; w++) mm = fmaxf(mm, s_max[w]);
        mm = fmaxf(mm, 1e-30f);
        s_scale[0] = mm / 127.0f;
        s_scale[1] = 127.0f / mm;
        g_sh[b] = mm / 127.0f;
    }
    __syncthreads();
    float s = s_scale[0], inv_s = s_scale[1];
#pragma unroll
    for (int i = 0; i < 4; i++) {
        signed char h0, l0, h1, l1, h2, l2, h3, l3;
        q2(v[i].x, inv_s, s, h0, l0);
        q2(v[i].y, inv_s, s, h1, l1);
        q2(v[i].z, inv_s, s, h2, l2);
        q2(v[i].w, inv_s, s, h3, l3);
        reinterpret_cast<char4*>(qh)[tid + i * NTH] = make_char4(h0, h1, h2, h3);
        reinterpret_cast<char4*>(ql)[tid + i * NTH] = make_char4(l0, l1, l2, l3);
    }
}

// ---------------------------------------------------------------------------
// Kernel 3: GEMM1  H = gelu(gather(Xq) @ Wfcq[e]^T + b) -> fp32 g_h
// grid (T/128, F/128, E), int8 IMMA, 3-stage pipeline
// ---------------------------------------------------------------------------
__global__ void __launch_bounds__(NTH, 1)
k_fc_mma(const float* __restrict__ bfc) {
    int e = blockIdx.z;
    int cnt = g_cursor[e];
    int row0 = blockIdx.x * BM;
    if (row0 >= cnt) return;
    int n0 = blockIdx.y * BN;
    int hbase = expert_base(e);

    extern __shared__ __align__(1024) char smem[];
    __shared__ int s_toff[BM];
    int tid = threadIdx.x, wid = tid >> 5, lane = tid & 31;
    uint32_t sb = smem_u32(smem);

    if (tid < BM) s_toff[tid] = g_tok[e * T_ + min(row0 + tid, cnt - 1)] * D_;
    __syncthreads();

    int warp_m = wid >> 2, warp_n = wid & 3;
    int g = lane >> 3, l8 = lane & 7;
    int rA = (g & 1) * 8 + l8, bA = (g >> 1) * 16;
    int rB = (g >> 1) * 8 + l8, bB = (g & 1) * 16;

    // copy coords: per stage-array 512 16B units; 2 per thread (64B rows)
    int ur[2], uc[2];
#pragma unroll
    for (int j = 0; j < 2; j++) { int u = tid + j * NTH; ur[j] = u >> 2; uc[j] = u & 3; }

    const int8_t* wh = g_wfq_h + (size_t)e * F_ * D_;
    const int8_t* wl = g_wfq_l + (size_t)e * F_ * D_;

#define FC_ISSUE(ci, sg)                                                        \
    {                                                                           \
        uint32_t bufb = sb + (sg) * STAGE_B;                                    \
        int k0 = (ci) * KC;                                                     \
        _Pragma("unroll")                                                       \
        for (int j = 0; j < 2; j++) {                                           \
            uint32_t dst = SW64((uint32_t)(ur[j] * 64 + uc[j] * 16));           \
            size_t ao = (size_t)s_toff[ur[j]] + k0 + uc[j] * 16;                \
            size_t bo = (size_t)(n0 + ur[j]) * D_ + k0 + uc[j] * 16;            \
            CPA(bufb + AH_OFF + dst, g_xq_h + ao);                              \
            CPA(bufb + AL_OFF + dst, g_xq_l + ao);                              \
            CPA(bufb + BH_OFF + dst, wh + bo);                                  \
            CPA(bufb + BL_OFF + dst, wl + bo);                                  \
        }                                                                       \
        CPA_COMMIT();                                                           \
    }

    FC_ISSUE(0, 0);
    FC_ISSUE(1, 1);

    int c0[4][4][4], c1[4][4][4];
#pragma unroll
    for (int f = 0; f < 4; f++)
#pragma unroll
        for (int nf = 0; nf < 4; nf++)
#pragma unroll
            for (int q = 0; q < 4; q++) { c0[f][nf][q] = 0; c1[f][nf][q] = 0; }

    const int KCH = D_ / KC;   // 16
    int stage = 0;
    for (int i = 0; i < KCH; i++) {
        if (i < KCH - 1) asm volatile("cp.async.wait_group 1;" ::: "memory");
        else             asm volatile("cp.async.wait_group 0;" ::: "memory");
        __syncthreads();
        if (i + 2 < KCH) {
            int sg = stage + 2; if (sg >= NSTAGE) sg -= NSTAGE;
            FC_ISSUE(i + 2, sg);
        }
        mma_chunk_i8(sb + stage * STAGE_B, warp_m, warp_n, rA, bA, rB, bB, c0, c1);
        if (++stage == NSTAGE) stage = 0;
    }
#undef FC_ISSUE

    // Epilogue: scale-combine + bias + gelu -> fp32 g_h
    int qr = lane >> 2, qc = (lane & 3) * 2;
#pragma unroll
    for (int f = 0; f < 4; f++) {
#pragma unroll
        for (int pr = 0; pr < 2; pr++) {
            int rl = warp_m * 64 + f * 16 + qr + pr * 8;
            int r = row0 + rl;
            if (r >= cnt) continue;
            float sxv = g_sx[s_toff[rl] >> 10];   // token = offset / D_
            size_t hr = (size_t)(hbase + r);
#pragma unroll
            for (int nf = 0; nf < 4; nf++) {
                int n = n0 + warp_n * 32 + nf * 8 + qc;
                float sc0 = sxv * g_swf[e * F_ + n];
                float sc1 = sxv * g_swf[e * F_ + n + 1];
                float a0 = (float)c0[f][nf][pr * 2 + 0] + (float)c1[f][nf][pr * 2 + 0] * INV127;
                float a1 = (float)c0[f][nf][pr * 2 + 1] + (float)c1[f][nf][pr * 2 + 1] * INV127;
                float v0 = ngelu(a0 * sc0 + bfc[e * F_ + n]);
                float v1 = ngelu(a1 * sc1 + bfc[e * F_ + n + 1]);
                *reinterpret_cast<float2*>(g_h + hr * F_ + n) = make_float2(v0, v1);
            }
        }
    }
}

// ---------------------------------------------------------------------------
// Kernel 5: GEMM2  out[token] += w * (Hq @ Wprojq[e]^T + b)
// grid (T/128, D/128, E)
// ---------------------------------------------------------------------------
__global__ void __launch_bounds__(NTH, 1)
k_proj_mma(const float* __restrict__ bpj, float* __restrict__ out) {
    int e = blockIdx.z;
    int cnt = g_cursor[e];
    int row0 = blockIdx.x * BM;
    if (row0 >= cnt) return;
    int n0 = blockIdx.y * BN;
    int hbase = expert_base(e);

    extern __shared__ __align__(1024) char smem[];
    __shared__ int   s_hrow[BM];
    __shared__ int   s_tok[BM];
    __shared__ float s_wgt[BM];
    int tid = threadIdx.x, wid = tid >> 5, lane = tid & 31;
    uint32_t sb = smem_u32(smem);

    if (tid < BM) {
        int r = min(row0 + tid, cnt - 1);
        s_hrow[tid] = hbase + r;
        s_tok[tid]  = g_tok[e * T_ + r];
        s_wgt[tid]  = g_wgt[e * T_ + r];
    }
    __syncthreads();

    int warp_m = wid >> 2, warp_n = wid & 3;
    int g = lane >> 3, l8 = lane & 7;
    int rA = (g & 1) * 8 + l8, bA = (g >> 1) * 16;
    int rB = (g >> 1) * 8 + l8, bB = (g & 1) * 16;

    int ur[2], uc[2];
#pragma unroll
    for (int j = 0; j < 2; j++) { int u = tid + j * NTH; ur[j] = u >> 2; uc[j] = u & 3; }

    const int8_t* wh = g_wpq_h + (size_t)e * D_ * F_;
    const int8_t* wl = g_wpq_l + (size_t)e * D_ * F_;

#define PJ_ISSUE(ci, sg)                                                        \
    {                                                                           \
        uint32_t bufb = sb + (sg) * STAGE_B;                                    \
        int k0 = (ci) * KC;                                                     \
        _Pragma("unroll")                                                       \
        for (int j = 0; j < 2; j++) {                                           \
            uint32_t dst = SW64((uint32_t)(ur[j] * 64 + uc[j] * 16));           \
            size_t ao = (size_t)s_hrow[ur[j]] * F_ + k0 + uc[j] * 16;           \
            size_t bo = (size_t)(n0 + ur[j]) * F_ + k0 + uc[j] * 16;            \
            CPA(bufb + AH_OFF + dst, g_hq_h + ao);                              \
            CPA(bufb + AL_OFF + dst, g_hq_l + ao);                              \
            CPA(bufb + BH_OFF + dst, wh + bo);                                  \
            CPA(bufb + BL_OFF + dst, wl + bo);                                  \
        }                                                                       \
        CPA_COMMIT();                                                           \
    }

    PJ_ISSUE(0, 0);
    PJ_ISSUE(1, 1);

    int c0[4][4][4], c1[4][4][4];
#pragma unroll
    for (int f = 0; f < 4; f++)
#pragma unroll
        for (int nf = 0; nf < 4; nf++)
#pragma unroll
            for (int q = 0; q < 4; q++) { c0[f][nf][q] = 0; c1[f][nf][q] = 0; }

    const int KCH = F_ / KC;   // 64
    int stage = 0;
    for (int i = 0; i < KCH; i++) {
        if (i < KCH - 1) asm volatile("cp.async.wait_group 1;" ::: "memory");
        else             asm volatile("cp.async.wait_group 0;" ::: "memory");
        __syncthreads();
        if (i + 2 < KCH) {
            int sg = stage + 2; if (sg >= NSTAGE) sg -= NSTAGE;
            PJ_ISSUE(i + 2, sg);
        }
        mma_chunk_i8(sb + stage * STAGE_B, warp_m, warp_n, rA, bA, rB, bB, c0, c1);
        if (++stage == NSTAGE) stage = 0;
    }
#undef PJ_ISSUE

    // Epilogue: scale-combine + bias, * routing weight, atomic scatter
    int qr = lane >> 2, qc = (lane & 3) * 2;
#pragma unroll
    for (int f = 0; f < 4; f++) {
#pragma unroll
        for (int pr = 0; pr < 2; pr++) {
            int rl = warp_m * 64 + f * 16 + qr + pr * 8;
            int r = row0 + rl;
            if (r >= cnt) continue;
            int   token = s_tok[rl];
            float w     = s_wgt[rl];
            float shv   = g_sh[s_hrow[rl]];
            float* orow = out + (size_t)token * D_;
#pragma unroll
            for (int nf = 0; nf < 4; nf++) {
                int n = n0 + warp_n * 32 + nf * 8 + qc;
                float sc0 = shv * g_swp[e * D_ + n];
                float sc1 = shv * g_swp[e * D_ + n + 1];
                float a0 = (float)c0[f][nf][pr * 2 + 0] + (float)c1[f][nf][pr * 2 + 0] * INV127;
                float a1 = (float)c0[f][nf][pr * 2 + 1] + (float)c1[f][nf][pr * 2 + 1] * INV127;
                atomicAdd(orow + n,     (a0 * sc0 + bpj[e * D_ + n])     * w);
                atomicAdd(orow + n + 1, (a1 * sc1 + bpj[e * D_ + n + 1]) * w);
            }
        }
    }
}

// ---------------------------------------------------------------------------
// Launch: zero, gate, quantA, fc (ncu slot 3), quantH, proj
// ---------------------------------------------------------------------------
extern "C" void kernel_launch(void* const* d_in, const int* in_sizes, int n_in,
                              void* d_out, int out_size) {
    const float* x   = (const float*)d_in[0];
    const float* gw  = (const float*)d_in[1];
    const float* wfc = (const float*)d_in[2];
    const float* bfc = (const float*)d_in[3];
    const float* wpj = (const float*)d_in[4];
    const float* bpj = (const float*)d_in[5];
    float* out = (float*)d_out;

    cudaFuncSetAttribute(k_fc_mma,   cudaFuncAttributeMaxDynamicSharedMemorySize, SMEM_DYN);
    cudaFuncSetAttribute(k_proj_mma, cudaFuncAttributeMaxDynamicSharedMemorySize, SMEM_DYN);

    k_zero  <<<2048, 256>>>(out, out_size);                                    // 0
    k_gate  <<<T_ / 8, 256>>>(x, gw);                                          // 1
    k_quantA<<<T_ + E_ * F_ + E_ * D_, NTH>>>(x, wfc, wpj);                    // 2
    k_fc_mma  <<<dim3(T_ / BM, F_ / BN, E_), NTH, SMEM_DYN>>>(bfc);            // 3 <- ncu
    k_quantH<<<TK_, NTH>>>();                                                  // 4
    k_proj_mma<<<dim3(T_ / BM, D_ / BN, E_), NTH, SMEM_DYN>>>(bpj, out);       // 5
}

// round 14
// speedup vs baseline: 1.8159x; 1.0462x over previous
#include <cuda_runtime.h>
#include <cuda_bf16.h>
#include <math.h>
#include <stdint.h>

// Problem constants
#define E_  8
#define D_  1024
#define F_  4096
#define T_  8192
#define TK_ (T_ * 2)

// GEMM tiling: 128x128 block, 512 threads (16 warps, 4/SMSP), warp tile 32x32,
// KC=64 int8 chunk (64B rows, SW64 swizzle), 3-stage cp.async pipeline.
#define BM 128
#define BN 128
#define KC 64
#define NTH 512
#define AH_OFF 0
#define AL_OFF 8192
#define BH_OFF 16384
#define BL_OFF 24576
#define STAGE_B 32768
#define NSTAGE 3
#define SMEM_DYN (NSTAGE * STAGE_B)   // 96 KB

#define INV127 0.007874015748031496f

// ---------------------------------------------------------------------------
// Device scratch (static: no allocations allowed)
// ---------------------------------------------------------------------------
__device__ int8_t g_xq_h[(size_t)T_ * D_];
__device__ int8_t g_xq_l[(size_t)T_ * D_];
__device__ int8_t g_wfq_h[(size_t)E_ * F_ * D_];
__device__ int8_t g_wfq_l[(size_t)E_ * F_ * D_];
__device__ int8_t g_wpq_h[(size_t)E_ * D_ * F_];
__device__ int8_t g_wpq_l[(size_t)E_ * D_ * F_];
__device__ int8_t g_hq_h[(size_t)TK_ * F_];
__device__ int8_t g_hq_l[(size_t)TK_ * F_];
__device__ float  g_h[(size_t)TK_ * F_];      // fp32 h before quantization
__device__ float  g_sx[T_];
__device__ float  g_swf[E_ * F_];
__device__ float  g_swp[E_ * D_];
__device__ float  g_sh[TK_];
__device__ int    g_tok[E_ * T_];
__device__ float  g_wgt[E_ * T_];
__device__ int    g_cursor[E_];

// ---------------------------------------------------------------------------
// Helpers
// ---------------------------------------------------------------------------
static __device__ __forceinline__ uint32_t smem_u32(const void* p) {
    uint32_t a;
    asm("{ .reg .u64 t; cvta.to.shared.u64 t, %1; cvt.u32.u64 %0, t; }"
        : "=r"(a) : "l"(p));
    return a;
}

// 64B-row swizzle (validated R7/R8/R12)
#define SW64(o) ((o) ^ (((o) >> 3) & 0x30))

#define CPA(dst, src) \
    asm volatile("cp.async.cg.shared.global [%0], [%1], 16;" \
                 :: "r"(dst), "l"(src) : "memory")
#define CPA_COMMIT() asm volatile("cp.async.commit_group;" ::: "memory")

#define LDSM4(r, addr) \
    asm volatile("ldmatrix.sync.aligned.m8n8.x4.shared.b16 {%0,%1,%2,%3}, [%4];" \
                 : "=r"((r)[0]), "=r"((r)[1]), "=r"((r)[2]), "=r"((r)[3]) \
                 : "r"(addr))

#define IMMA(cd, a, b0, b1) \
    asm volatile("mma.sync.aligned.m16n8k32.row.col.s32.s8.s8.s32 " \
                 "{%0,%1,%2,%3}, {%4,%5,%6,%7}, {%8,%9}, {%0,%1,%2,%3};" \
                 : "+r"((cd)[0]), "+r"((cd)[1]), "+r"((cd)[2]), "+r"((cd)[3]) \
                 : "r"((a)[0]), "r"((a)[1]), "r"((a)[2]), "r"((a)[3]), \
                   "r"(b0), "r"(b1))

static __device__ __forceinline__ float ngelu(float v) {
    float u = 0.7978845608028654f * (v + 0.044715f * v * v * v);
    return 0.5f * v * (1.0f + tanhf(u));
}

static __device__ __forceinline__ int expert_base(int e) {
    int b = 0;
#pragma unroll
    for (int j = 0; j < E_; j++) if (j < e) b += g_cursor[j];
    return b;
}

// Quantize one fp32 to (hi, lo) int8 given inv_s = 127/rowmax, s = rowmax/127
static __device__ __forceinline__ void q2(float v, float inv_s, float s,
                                          signed char& qh, signed char& ql) {
    int a = __float2int_rn(v * inv_s);
    float r = v - s * (float)a;
    int b = __float2int_rn(r * inv_s * 127.0f);
    qh = (signed char)a;
    ql = (signed char)b;
}

// One K=64 int8 chunk, register-lean term-by-term schedule (warp tile 32x32):
//   C0 += Ah*Bh;  C1 += Al*Bh;  (Bh regs overwritten with Bl)  C1 += Ah*Bl.
// Live frags: Ah 8 + Al 8 + Bx 8 = 24 regs; accums 64.
static __device__ __forceinline__ void mma_chunk_i8(
    uint32_t bufb, int warp_m, int warp_n,
    int rA, int bA, int rB, int bB, int (&c0)[2][4][4], int (&c1)[2][4][4]) {
#pragma unroll
    for (int ks = 0; ks < 2; ks++) {
        int kb = ks * 32;
        uint32_t Ah[2][4], Al[2][4], Bx[2][4];
#pragma unroll
        for (int f = 0; f < 2; f++) {
            uint32_t off = (uint32_t)((warp_m * 32 + f * 16 + rA) * 64 + kb + bA);
            LDSM4(Ah[f], bufb + AH_OFF + SW64(off));
        }
#pragma unroll
        for (int p = 0; p < 2; p++) {
            uint32_t off = (uint32_t)((warp_n * 32 + p * 16 + rB) * 64 + kb + bB);
            LDSM4(Bx[p], bufb + BH_OFF + SW64(off));
        }
#pragma unroll
        for (int f = 0; f < 2; f++)
#pragma unroll
            for (int nf = 0; nf < 4; nf++)
                IMMA(c0[f][nf], Ah[f], Bx[nf >> 1][(nf & 1) * 2], Bx[nf >> 1][(nf & 1) * 2 + 1]);
#pragma unroll
        for (int f = 0; f < 2; f++) {
            uint32_t off = (uint32_t)((warp_m * 32 + f * 16 + rA) * 64 + kb + bA);
            LDSM4(Al[f], bufb + AL_OFF + SW64(off));
        }
#pragma unroll
        for (int f = 0; f < 2; f++)
#pragma unroll
            for (int nf = 0; nf < 4; nf++)
                IMMA(c1[f][nf], Al[f], Bx[nf >> 1][(nf & 1) * 2], Bx[nf >> 1][(nf & 1) * 2 + 1]);
#pragma unroll
        for (int p = 0; p < 2; p++) {
            uint32_t off = (uint32_t)((warp_n * 32 + p * 16 + rB) * 64 + kb + bB);
            LDSM4(Bx[p], bufb + BL_OFF + SW64(off));
        }
#pragma unroll
        for (int f = 0; f < 2; f++)
#pragma unroll
            for (int nf = 0; nf < 4; nf++)
                IMMA(c1[f][nf], Ah[f], Bx[nf >> 1][(nf & 1) * 2], Bx[nf >> 1][(nf & 1) * 2 + 1]);
    }
}

// ---------------------------------------------------------------------------
// Kernel 0: reset cursors + zero output
// ---------------------------------------------------------------------------
__global__ void k_zero(float* __restrict__ out, int n_elems) {
    if (blockIdx.x == 0 && threadIdx.x < E_) g_cursor[threadIdx.x] = 0;
    int i = blockIdx.x * blockDim.x + threadIdx.x;
    int stride = gridDim.x * blockDim.x;
    float4 z = make_float4(0.f, 0.f, 0.f, 0.f);
    for (int idx = i; idx * 4 < n_elems; idx += stride)
        reinterpret_cast<float4*>(out)[idx] = z;
}

// ---------------------------------------------------------------------------
// Kernel 1: gating (one warp per token)
// ---------------------------------------------------------------------------
__global__ void k_gate(const float* __restrict__ x, const float* __restrict__ gw) {
    int warp = threadIdx.x >> 5;
    int lane = threadIdx.x & 31;
    int t = blockIdx.x * 8 + warp;
    const float* xr = x + (size_t)t * D_;

    float xv[32];
#pragma unroll
    for (int i = 0; i < 32; i++) xv[i] = xr[i * 32 + lane];

    float logit[E_];
#pragma unroll
    for (int e = 0; e < E_; e++) {
        const float* wr = gw + e * D_;
        float acc = 0.f;
#pragma unroll
        for (int i = 0; i < 32; i++) acc = fmaf(xv[i], wr[i * 32 + lane], acc);
#pragma unroll
        for (int s = 16; s > 0; s >>= 1) acc += __shfl_xor_sync(0xffffffffu, acc, s);
        logit[e] = acc;
    }

    if (lane == 0) {
        int e0 = 0;
#pragma unroll
        for (int e = 1; e < E_; e++) if (logit[e] > logit[e0]) e0 = e;
        int e1 = (e0 == 0) ? 1 : 0;
#pragma unroll
        for (int e = 0; e < E_; e++) if (e != e0 && logit[e] > logit[e1]) e1 = e;

        float m  = logit[e0];
        float x0 = expf(logit[e0] - m);
        float x1 = expf(logit[e1] - m);
        float inv = 1.f / (x0 + x1);

        int p0 = atomicAdd(&g_cursor[e0], 1);
        g_tok[e0 * T_ + p0] = t;  g_wgt[e0 * T_ + p0] = x0 * inv;
        int p1 = atomicAdd(&g_cursor[e1], 1);
        g_tok[e1 * T_ + p1] = t;  g_wgt[e1 * T_ + p1] = x1 * inv;
    }
}

// ---------------------------------------------------------------------------
// Kernel 2: row-wise 2-level int8 quantization of x, wfc, wpj (256 threads)
// ---------------------------------------------------------------------------
#define QTH 256
__global__ void k_quantA(const float* __restrict__ x,
                         const float* __restrict__ wfc,
                         const float* __restrict__ wpj) {
    __shared__ float s_max[8];
    __shared__ float s_scale[2];
    int b = blockIdx.x, tid = threadIdx.x;

    const float* row; int8_t *qh, *ql; float* sc; int nvec;
    if (b < T_) {
        row = x + (size_t)b * D_;
        qh = g_xq_h + (size_t)b * D_;  ql = g_xq_l + (size_t)b * D_;
        sc = &g_sx[b]; nvec = 1;
    } else if (b < T_ + E_ * F_) {
        int r = b - T_;
        row = wfc + (size_t)r * D_;
        qh = g_wfq_h + (size_t)r * D_; ql = g_wfq_l + (size_t)r * D_;
        sc = &g_swf[r]; nvec = 1;
    } else {
        int r = b - T_ - E_ * F_;
        row = wpj + (size_t)r * F_;
        qh = g_wpq_h + (size_t)r * F_; ql = g_wpq_l + (size_t)r * F_;
        sc = &g_swp[r]; nvec = 4;
    }

    float4 v[4];
    float m = 0.f;
    for (int i = 0; i < nvec; i++) {
        v[i] = reinterpret_cast<const float4*>(row)[tid + i * QTH];
        m = fmaxf(m, fmaxf(fmaxf(fabsf(v[i].x), fabsf(v[i].y)),
                           fmaxf(fabsf(v[i].z), fabsf(v[i].w))));
    }
#pragma unroll
    for (int s = 16; s > 0; s >>= 1) m = fmaxf(m, __shfl_xor_sync(0xffffffffu, m, s));
    if ((tid & 31) == 0) s_max[tid >> 5] = m;
    __syncthreads();
    if (tid == 0) {
        float mm = s_max[0];
#pragma unroll
        for (int w = 1; w < 8; w++) mm = fmaxf(mm, s_max[w]);
        mm = fmaxf(mm, 1e-30f);
        s_scale[0] = mm / 127.0f;
        s_scale[1] = 127.0f / mm;
        *sc = mm / 127.0f;
    }
    __syncthreads();
    float s = s_scale[0], inv_s = s_scale[1];

    for (int i = 0; i < nvec; i++) {
        signed char h0, l0, h1, l1, h2, l2, h3, l3;
        q2(v[i].x, inv_s, s, h0, l0);
        q2(v[i].y, inv_s, s, h1, l1);
        q2(v[i].z, inv_s, s, h2, l2);
        q2(v[i].w, inv_s, s, h3, l3);
        reinterpret_cast<char4*>(qh)[tid + i * QTH] = make_char4(h0, h1, h2, h3);
        reinterpret_cast<char4*>(ql)[tid + i * QTH] = make_char4(l0, l1, l2, l3);
    }
}

// ---------------------------------------------------------------------------
// Kernel 4: row-wise quantization of h (bucket-ordered, rows of F)
// ---------------------------------------------------------------------------
__global__ void k_quantH() {
    __shared__ float s_max[8];
    __shared__ float s_scale[2];
    int b = blockIdx.x, tid = threadIdx.x;
    const float* row = g_h + (size_t)b * F_;
    int8_t* qh = g_hq_h + (size_t)b * F_;
    int8_t* ql = g_hq_l + (size_t)b * F_;

    float4 v[4];
    float m = 0.f;
#pragma unroll
    for (int i = 0; i < 4; i++) {
        v[i] = reinterpret_cast<const float4*>(row)[tid + i * QTH];
        m = fmaxf(m, fmaxf(fmaxf(fabsf(v[i].x), fabsf(v[i].y)),
                           fmaxf(fabsf(v[i].z), fabsf(v[i].w))));
    }
#pragma unroll
    for (int s = 16; s > 0; s >>= 1) m = fmaxf(m, __shfl_xor_sync(0xffffffffu, m, s));
    if ((tid & 31) == 0) s_max[tid >> 5] = m;
    __syncthreads();
    if (tid == 0) {
        float mm = s_max[0];
#pragma unroll
        for (int w = 1; w < 8; w++) mm = fmaxf(mm, s_max[w]);
        mm = fmaxf(mm, 1e-30f);
        s_scale[0] = mm / 127.0f;
        s_scale[1] = 127.0f / mm;
        g_sh[b] = mm / 127.0f;
    }
    __syncthreads();
    float s = s_scale[0], inv_s = s_scale[1];
#pragma unroll
    for (int i = 0; i < 4; i++) {
        signed char h0, l0, h1, l1, h2, l2, h3, l3;
        q2(v[i].x, inv_s, s, h0, l0);
        q2(v[i].y, inv_s, s, h1, l1);
        q2(v[i].z, inv_s, s, h2, l2);
        q2(v[i].w, inv_s, s, h3, l3);
        reinterpret_cast<char4*>(qh)[tid + i * QTH] = make_char4(h0, h1, h2, h3);
        reinterpret_cast<char4*>(ql)[tid + i * QTH] = make_char4(l0, l1, l2, l3);
    }
}

// ---------------------------------------------------------------------------
// Kernel 3: GEMM1  H = gelu(gather(Xq) @ Wfcq[e]^T + b) -> fp32 g_h
// grid (T/128, F/128, E), 512 threads, warp tile 32x32, int8 IMMA
// ---------------------------------------------------------------------------
__global__ void __launch_bounds__(NTH, 1)
k_fc_mma(const float* __restrict__ bfc) {
    int e = blockIdx.z;
    int cnt = g_cursor[e];
    int row0 = blockIdx.x * BM;
    if (row0 >= cnt) return;
    int n0 = blockIdx.y * BN;
    int hbase = expert_base(e);

    extern __shared__ __align__(1024) char smem[];
    __shared__ int s_toff[BM];
    int tid = threadIdx.x, wid = tid >> 5, lane = tid & 31;
    uint32_t sb = smem_u32(smem);

    if (tid < BM) s_toff[tid] = g_tok[e * T_ + min(row0 + tid, cnt - 1)] * D_;
    __syncthreads();

    int warp_m = wid >> 2, warp_n = wid & 3;   // 4 x 4 warps, tile 32x32
    int g = lane >> 3, l8 = lane & 7;
    int rA = (g & 1) * 8 + l8, bA = (g >> 1) * 16;
    int rB = (g >> 1) * 8 + l8, bB = (g & 1) * 16;

    // copy coords: per stage-array 512 16B units; 1 per thread (64B rows)
    int ur = tid >> 2, uc = tid & 3;

    const int8_t* wh = g_wfq_h + (size_t)e * F_ * D_;
    const int8_t* wl = g_wfq_l + (size_t)e * F_ * D_;

#define FC_ISSUE(ci, sg)                                                        \
    {                                                                           \
        uint32_t bufb = sb + (sg) * STAGE_B;                                    \
        int k0 = (ci) * KC;                                                     \
        uint32_t dst = SW64((uint32_t)(ur * 64 + uc * 16));                     \
        size_t ao = (size_t)s_toff[ur] + k0 + uc * 16;                          \
        size_t bo = (size_t)(n0 + ur) * D_ + k0 + uc * 16;                      \
        CPA(bufb + AH_OFF + dst, g_xq_h + ao);                                  \
        CPA(bufb + AL_OFF + dst, g_xq_l + ao);                                  \
        CPA(bufb + BH_OFF + dst, wh + bo);                                      \
        CPA(bufb + BL_OFF + dst, wl + bo);                                      \
        CPA_COMMIT();                                                           \
    }

    FC_ISSUE(0, 0);
    FC_ISSUE(1, 1);

    int c0[2][4][4], c1[2][4][4];
#pragma unroll
    for (int f = 0; f < 2; f++)
#pragma unroll
        for (int nf = 0; nf < 4; nf++)
#pragma unroll
            for (int q = 0; q < 4; q++) { c0[f][nf][q] = 0; c1[f][nf][q] = 0; }

    const int KCH = D_ / KC;   // 16
    int stage = 0;
    for (int i = 0; i < KCH; i++) {
        if (i < KCH - 1) asm volatile("cp.async.wait_group 1;" ::: "memory");
        else             asm volatile("cp.async.wait_group 0;" ::: "memory");
        __syncthreads();
        if (i + 2 < KCH) {
            int sg = stage + 2; if (sg >= NSTAGE) sg -= NSTAGE;
            FC_ISSUE(i + 2, sg);
        }
        mma_chunk_i8(sb + stage * STAGE_B, warp_m, warp_n, rA, bA, rB, bB, c0, c1);
        if (++stage == NSTAGE) stage = 0;
    }
#undef FC_ISSUE

    // Epilogue: scale-combine + bias + gelu -> fp32 g_h
    int qr = lane >> 2, qc = (lane & 3) * 2;
#pragma unroll
    for (int f = 0; f < 2; f++) {
#pragma unroll
        for (int pr = 0; pr < 2; pr++) {
            int rl = warp_m * 32 + f * 16 + qr + pr * 8;
            int r = row0 + rl;
            if (r >= cnt) continue;
            float sxv = g_sx[s_toff[rl] >> 10];   // token = offset / D_
            size_t hr = (size_t)(hbase + r);
#pragma unroll
            for (int nf = 0; nf < 4; nf++) {
                int n = n0 + warp_n * 32 + nf * 8 + qc;
                float sc0 = sxv * g_swf[e * F_ + n];
                float sc1 = sxv * g_swf[e * F_ + n + 1];
                float a0 = (float)c0[f][nf][pr * 2 + 0] + (float)c1[f][nf][pr * 2 + 0] * INV127;
                float a1 = (float)c0[f][nf][pr * 2 + 1] + (float)c1[f][nf][pr * 2 + 1] * INV127;
                float v0 = ngelu(a0 * sc0 + bfc[e * F_ + n]);
                float v1 = ngelu(a1 * sc1 + bfc[e * F_ + n + 1]);
                *reinterpret_cast<float2*>(g_h + hr * F_ + n) = make_float2(v0, v1);
            }
        }
    }
}

// ---------------------------------------------------------------------------
// Kernel 5: GEMM2  out[token] += w * (Hq @ Wprojq[e]^T + b)
// grid (T/128, D/128, E), 512 threads
// ---------------------------------------------------------------------------
__global__ void __launch_bounds__(NTH, 1)
k_proj_mma(const float* __restrict__ bpj, float* __restrict__ out) {
    int e = blockIdx.z;
    int cnt = g_cursor[e];
    int row0 = blockIdx.x * BM;
    if (row0 >= cnt) return;
    int n0 = blockIdx.y * BN;
    int hbase = expert_base(e);

    extern __shared__ __align__(1024) char smem[];
    __shared__ int   s_hrow[BM];
    __shared__ int   s_tok[BM];
    __shared__ float s_wgt[BM];
    int tid = threadIdx.x, wid = tid >> 5, lane = tid & 31;
    uint32_t sb = smem_u32(smem);

    if (tid < BM) {
        int r = min(row0 + tid, cnt - 1);
        s_hrow[tid] = hbase + r;
        s_tok[tid]  = g_tok[e * T_ + r];
        s_wgt[tid]  = g_wgt[e * T_ + r];
    }
    __syncthreads();

    int warp_m = wid >> 2, warp_n = wid & 3;
    int g = lane >> 3, l8 = lane & 7;
    int rA = (g & 1) * 8 + l8, bA = (g >> 1) * 16;
    int rB = (g >> 1) * 8 + l8, bB = (g & 1) * 16;

    int ur = tid >> 2, uc = tid & 3;

    const int8_t* wh = g_wpq_h + (size_t)e * D_ * F_;
    const int8_t* wl = g_wpq_l + (size_t)e * D_ * F_;

#define PJ_ISSUE(ci, sg)                                                        \
    {                                                                           \
        uint32_t bufb = sb + (sg) * STAGE_B;                                    \
        int k0 = (ci) * KC;                                                     \
        uint32_t dst = SW64((uint32_t)(ur * 64 + uc * 16));                     \
        size_t ao = (size_t)s_hrow[ur] * F_ + k0 + uc * 16;                     \
        size_t bo = (size_t)(n0 + ur) * F_ + k0 + uc * 16;                      \
        CPA(bufb + AH_OFF + dst, g_hq_h + ao);                                  \
        CPA(bufb + AL_OFF + dst, g_hq_l + ao);                                  \
        CPA(bufb + BH_OFF + dst, wh + bo);                                      \
        CPA(bufb + BL_OFF + dst, wl + bo);                                      \
        CPA_COMMIT();                                                           \
    }

    PJ_ISSUE(0, 0);
    PJ_ISSUE(1, 1);

    int c0[2][4][4], c1[2][4][4];
#pragma unroll
    for (int f = 0; f < 2; f++)
#pragma unroll
        for (int nf = 0; nf < 4; nf++)
#pragma unroll
            for (int q = 0; q < 4; q++) { c0[f][nf][q] = 0; c1[f][nf][q] = 0; }

    const int KCH = F_ / KC;   // 64
    int stage = 0;
    for (int i = 0; i < KCH; i++) {
        if (i < KCH - 1) asm volatile("cp.async.wait_group 1;" ::: "memory");
        else             asm volatile("cp.async.wait_group 0;" ::: "memory");
        __syncthreads();
        if (i + 2 < KCH) {
            int sg = stage + 2; if (sg >= NSTAGE) sg -= NSTAGE;
            PJ_ISSUE(i + 2, sg);
        }
        mma_chunk_i8(sb + stage * STAGE_B, warp_m, warp_n, rA, bA, rB, bB, c0, c1);
        if (++stage == NSTAGE) stage = 0;
    }
#undef PJ_ISSUE

    // Epilogue: scale-combine + bias, * routing weight, atomic scatter
    int qr = lane >> 2, qc = (lane & 3) * 2;
#pragma unroll
    for (int f = 0; f < 2; f++) {
#pragma unroll
        for (int pr = 0; pr < 2; pr++) {
            int rl = warp_m * 32 + f * 16 + qr + pr * 8;
            int r = row0 + rl;
            if (r >= cnt) continue;
            int   token = s_tok[rl];
            float w     = s_wgt[rl];
            float shv   = g_sh[s_hrow[rl]];
            float* orow = out + (size_t)token * D_;
#pragma unroll
            for (int nf = 0; nf < 4; nf++) {
                int n = n0 + warp_n * 32 + nf * 8 + qc;
                float sc0 = shv * g_swp[e * D_ + n];
                float sc1 = shv * g_swp[e * D_ + n + 1];
                float a0 = (float)c0[f][nf][pr * 2 + 0] + (float)c1[f][nf][pr * 2 + 0] * INV127;
                float a1 = (float)c0[f][nf][pr * 2 + 1] + (float)c1[f][nf][pr * 2 + 1] * INV127;
                atomicAdd(orow + n,     (a0 * sc0 + bpj[e * D_ + n])     * w);
                atomicAdd(orow + n + 1, (a1 * sc1 + bpj[e * D_ + n + 1]) * w);
            }
        }
    }
}

// ---------------------------------------------------------------------------
// Launch: zero, gate, quantA, fc (ncu slot 3), quantH, proj
// ---------------------------------------------------------------------------
extern "C" void kernel_launch(void* const* d_in, const int* in_sizes, int n_in,
                              void* d_out, int out_size) {
    const float* x   = (const float*)d_in[0];
    const float* gw  = (const float*)d_in[1];
    const float* wfc = (const float*)d_in[2];
    const float* bfc = (const float*)d_in[3];
    const float* wpj = (const float*)d_in[4];
    const float* bpj = (const float*)d_in[5];
    float* out = (float*)d_out;

    cudaFuncSetAttribute(k_fc_mma,   cudaFuncAttributeMaxDynamicSharedMemorySize, SMEM_DYN);
    cudaFuncSetAttribute(k_proj_mma, cudaFuncAttributeMaxDynamicSharedMemorySize, SMEM_DYN);

    k_zero  <<<2048, 256>>>(out, out_size);                                    // 0
    k_gate  <<<T_ / 8, 256>>>(x, gw);                                          // 1
    k_quantA<<<T_ + E_ * F_ + E_ * D_, QTH>>>(x, wfc, wpj);                    // 2
    k_fc_mma  <<<dim3(T_ / BM, F_ / BN, E_), NTH, SMEM_DYN>>>(bfc);            // 3 <- ncu
    k_quantH<<<TK_, QTH>>>();                                                  // 4
    k_proj_mma<<<dim3(T_ / BM, D_ / BN, E_), NTH, SMEM_DYN>>>(bpj, out);       // 5
}